// round 9
// baseline (speedup 1.0000x reference)
#include <cuda_runtime.h>
#include <cuda_bf16.h>
#include <cuda_fp16.h>
#include <math.h>

// ---------------------------------------------------------------------------
// Problem constants
// ---------------------------------------------------------------------------
#define BATCH   16384
#define NHIST   50
#define DIM     128
#define NITEMS  100000

// ---------------------------------------------------------------------------
// Scratch (static device globals)
// ---------------------------------------------------------------------------
__device__ __nv_bfloat16 g_KV[NITEMS * 256];   // per item: 128 bf16 K | 128 bf16 V
__device__ float g_Qg [BATCH * DIM];
__device__ float g_Q2 [BATCH * DIM];
__device__ float g_K0 [BATCH * DIM];
__device__ float g_V0 [BATCH * DIM];
__device__ float g_K1 [BATCH * DIM];
__device__ float g_V1 [BATCH * DIM];
__device__ float g_Y  [BATCH * DIM];
// bf16 weight splits, transposed to [n][k]: slot 2*w = hi, 2*w+1 = lo
// w: 0=gat_wq 1=gat_wk 2=gat_wv 3=gat_wo 4=sem_wq 5=sem_wk 6=sem_wv 7=sem_wo
__device__ unsigned short g_W4[16][DIM * DIM];
// fp16 transposed weights for the item GEMM: 0=gat_wk, 1=gat_wv
__device__ unsigned short g_Wh[2][DIM * DIM];

// ---------------------------------------------------------------------------
// helpers
// ---------------------------------------------------------------------------
__device__ __forceinline__ unsigned smem_u32(const void* p) {
    unsigned a;
    asm("{ .reg .u64 t; cvta.to.shared.u64 t, %1; cvt.u32.u64 %0, t; }"
        : "=r"(a) : "l"(p));
    return a;
}
__device__ __forceinline__ void ldm4(unsigned& r0, unsigned& r1,
                                     unsigned& r2, unsigned& r3, unsigned addr) {
    asm volatile("ldmatrix.sync.aligned.m8n8.x4.shared.b16 {%0,%1,%2,%3}, [%4];"
                 : "=r"(r0), "=r"(r1), "=r"(r2), "=r"(r3) : "r"(addr));
}
__device__ __forceinline__ void mma_bf16(float* d, const unsigned* a, const unsigned* b) {
    asm volatile("mma.sync.aligned.m16n8k16.row.col.f32.bf16.bf16.f32 "
                 "{%0,%1,%2,%3}, {%4,%5,%6,%7}, {%8,%9}, {%0,%1,%2,%3};"
                 : "+f"(d[0]), "+f"(d[1]), "+f"(d[2]), "+f"(d[3])
                 : "r"(a[0]), "r"(a[1]), "r"(a[2]), "r"(a[3]),
                   "r"(b[0]), "r"(b[1]));
}
__device__ __forceinline__ void mma_f16(float* d, const unsigned* a, const unsigned* b) {
    asm volatile("mma.sync.aligned.m16n8k16.row.col.f32.f16.f16.f32 "
                 "{%0,%1,%2,%3}, {%4,%5,%6,%7}, {%8,%9}, {%0,%1,%2,%3};"
                 : "+f"(d[0]), "+f"(d[1]), "+f"(d[2]), "+f"(d[3])
                 : "r"(a[0]), "r"(a[1]), "r"(a[2]), "r"(a[3]),
                   "r"(b[0]), "r"(b[1]));
}
// smem byte offset for (row, 8-elem 16B chunk kc): 256B rows, XOR swizzle
__device__ __forceinline__ unsigned sw_off(int row, int kc) {
    return (unsigned)(row * 256 + ((kc ^ (row & 7)) << 4));
}
// split 8 fp32 -> two uint4 of bf16 (hi, lo = residual)
__device__ __forceinline__ void split8(const float* xs, uint4& H, uint4& L) {
    unsigned hw[4], lw[4];
    #pragma unroll
    for (int j = 0; j < 4; j++) {
        __nv_bfloat16 h0 = __float2bfloat16(xs[2*j]);
        __nv_bfloat16 h1 = __float2bfloat16(xs[2*j+1]);
        __nv_bfloat16 l0 = __float2bfloat16(xs[2*j]   - __bfloat162float(h0));
        __nv_bfloat16 l1 = __float2bfloat16(xs[2*j+1] - __bfloat162float(h1));
        hw[j] = (unsigned)*(unsigned short*)&h0 | ((unsigned)*(unsigned short*)&h1 << 16);
        lw[j] = (unsigned)*(unsigned short*)&l0 | ((unsigned)*(unsigned short*)&l1 << 16);
    }
    H = make_uint4(hw[0], hw[1], hw[2], hw[3]);
    L = make_uint4(lw[0], lw[1], lw[2], lw[3]);
}
// 8 fp32 -> uint4 of bf16 (hi only)
__device__ __forceinline__ uint4 pack8bf(const float* xs) {
    unsigned hw[4];
    #pragma unroll
    for (int j = 0; j < 4; j++) {
        __nv_bfloat16 h0 = __float2bfloat16(xs[2*j]);
        __nv_bfloat16 h1 = __float2bfloat16(xs[2*j+1]);
        hw[j] = (unsigned)*(unsigned short*)&h0 | ((unsigned)*(unsigned short*)&h1 << 16);
    }
    return make_uint4(hw[0], hw[1], hw[2], hw[3]);
}
// 8 fp32 -> uint4 of fp16
__device__ __forceinline__ uint4 pack8f16(const float* xs) {
    unsigned hw[4];
    #pragma unroll
    for (int j = 0; j < 4; j++) {
        const unsigned short a = __half_as_ushort(__float2half_rn(xs[2*j]));
        const unsigned short b = __half_as_ushort(__float2half_rn(xs[2*j+1]));
        hw[j] = (unsigned)a | ((unsigned)b << 16);
    }
    return make_uint4(hw[0], hw[1], hw[2], hw[3]);
}
__device__ __forceinline__ unsigned pack_bf2(float a, float b) {
    __nv_bfloat16 x = __float2bfloat16(a), y = __float2bfloat16(b);
    return (unsigned)*(unsigned short*)&x | ((unsigned)*(unsigned short*)&y << 16);
}
// bf16x2 unpack via shift/mask
__device__ __forceinline__ float bflo(unsigned u) { return __uint_as_float(u << 16); }
__device__ __forceinline__ float bfhi(unsigned u) { return __uint_as_float(u & 0xffff0000u); }

// ===========================================================================
// Setup: transpose + split all weight matrices
// ===========================================================================
__global__ void w_setup(const float* w0, const float* w1, const float* w2,
                        const float* w3, const float* w4, const float* w5,
                        const float* w6, const float* w7)
{
    const int i = blockIdx.x * blockDim.x + threadIdx.x;
    if (i >= DIM * DIM) return;
    const float* ws[8] = {w0, w1, w2, w3, w4, w5, w6, w7};
    const int k = i >> 7, n = i & 127;
    const int dst = n * DIM + k;
    #pragma unroll
    for (int w = 0; w < 8; w++) {
        const float a = ws[w][i];
        __nv_bfloat16 h = __float2bfloat16(a);
        __nv_bfloat16 l = __float2bfloat16(a - __bfloat162float(h));
        g_W4[2*w    ][dst] = *(unsigned short*)&h;
        g_W4[2*w + 1][dst] = *(unsigned short*)&l;
    }
    g_Wh[0][dst] = __half_as_ushort(__float2half_rn(w1[i]));   // gat_wk
    g_Wh[1][dst] = __half_as_ushort(__float2half_rn(w2[i]));   // gat_wv
}

// ===========================================================================
// Shared GEMM building blocks. Warp layout: 8 warps (4x2), warp tile 32x64.
// TERMS=3: D = Ah*Wh + Ah*Wl + Al*Wh.  TERMS=1: D = Ah*Wh (score path).
// ===========================================================================
template<int TERMS>
__device__ __forceinline__ void mma_loop(
    unsigned sb, unsigned oAhi, unsigned oAlo, unsigned oWhi, unsigned oWlo,
    int wm, int wn, int lane, float acc[2][8][4])
{
    #pragma unroll
    for (int i = 0; i < 2; i++)
        #pragma unroll
        for (int j = 0; j < 8; j++)
            #pragma unroll
            for (int q = 0; q < 4; q++) acc[i][j][q] = 0.f;

    #pragma unroll
    for (int ks = 0; ks < 8; ks++) {
        unsigned aH[2][4], aL[2][4], bH[8][2], bL[8][2];
        {
            const int r  = wm * 32 + (lane & 15);
            const int kc = ks * 2 + (lane >> 4);
            ldm4(aH[0][0], aH[0][1], aH[0][2], aH[0][3], sb + oAhi + sw_off(r,      kc));
            ldm4(aH[1][0], aH[1][1], aH[1][2], aH[1][3], sb + oAhi + sw_off(r + 16, kc));
            if (TERMS == 3) {
                ldm4(aL[0][0], aL[0][1], aL[0][2], aL[0][3], sb + oAlo + sw_off(r,      kc));
                ldm4(aL[1][0], aL[1][1], aL[1][2], aL[1][3], sb + oAlo + sw_off(r + 16, kc));
            }
        }
        {
            const int grp  = lane >> 3;
            const int nloc = (lane & 7) + ((grp >> 1) << 3);
            const int kc   = ks * 2 + (grp & 1);
            #pragma unroll
            for (int j = 0; j < 4; j++) {
                const int n = wn * 64 + j * 16 + nloc;
                ldm4(bH[2*j][0], bH[2*j][1], bH[2*j+1][0], bH[2*j+1][1],
                     sb + oWhi + sw_off(n, kc));
                if (TERMS == 3)
                    ldm4(bL[2*j][0], bL[2*j][1], bL[2*j+1][0], bL[2*j+1][1],
                         sb + oWlo + sw_off(n, kc));
            }
        }
        #pragma unroll
        for (int mf = 0; mf < 2; mf++)
            #pragma unroll
            for (int nf = 0; nf < 8; nf++) {
                mma_bf16(acc[mf][nf], aH[mf], bH[nf]);
                if (TERMS == 3) {
                    mma_bf16(acc[mf][nf], aH[mf], bL[nf]);
                    mma_bf16(acc[mf][nf], aL[mf], bH[nf]);
                }
            }
    }
}

__device__ __forceinline__ void epi_f32(
    float acc[2][8][4], const float* sbias, float* C,
    int rowBase, int wm, int wn, int lane, int M)
{
    #pragma unroll
    for (int mf = 0; mf < 2; mf++) {
        const int r0 = rowBase + wm * 32 + mf * 16 + (lane >> 2);
        #pragma unroll
        for (int nf = 0; nf < 8; nf++) {
            const int c  = wn * 64 + nf * 8 + (lane & 3) * 2;
            const float b0 = sbias[c], b1 = sbias[c + 1];
            if (r0 < M)
                *(float2*)(C + (long)r0 * DIM + c) =
                    make_float2(fmaxf(acc[mf][nf][0] + b0, 0.f),
                                fmaxf(acc[mf][nf][1] + b1, 0.f));
            if (r0 + 8 < M)
                *(float2*)(C + (long)(r0 + 8) * DIM + c) =
                    make_float2(fmaxf(acc[mf][nf][2] + b0, 0.f),
                                fmaxf(acc[mf][nf][3] + b1, 0.f));
        }
    }
}

__device__ __forceinline__ void stage_w(
    char* sm, unsigned oWhi, unsigned oWlo, int wslot, int tid)
{
    const unsigned short* WH = g_W4[2 * wslot];
    const unsigned short* WL = g_W4[2 * wslot + 1];
    #pragma unroll
    for (int u = 0; u < 8; u++) {
        const int g  = u * 256 + tid;
        const int n  = g >> 4, kc = g & 15;
        const unsigned o = sw_off(n, kc);
        *(uint4*)(sm + oWhi + o) = *(const uint4*)(WH + n * DIM + kc * 8);
        *(uint4*)(sm + oWlo + o) = *(const uint4*)(WL + n * DIM + kc * 8);
    }
}

// ===========================================================================
// Node transforms: 4 weight sets via blockIdx.y, per-set term count.
// smem: A-hi 32K | A-lo 32K | W-hi 32K | W-lo 32K | bias
// ===========================================================================
#define NSM_AHI  0u
#define NSM_ALO  32768u
#define NSM_WHI  65536u
#define NSM_WLO  98304u
#define NSM_BIAS 131072u
#define NSMEM    131584

struct HSet { int wslot; const float* bias; float* C; int terms; };

__global__ void __launch_bounds__(256)
gemm_hmma(const float* __restrict__ A, const int* __restrict__ gidx,
          HSet s0, HSet s1, HSet s2, HSet s3, int M)
{
    const HSet s = (blockIdx.y == 0) ? s0 : (blockIdx.y == 1) ? s1
                 : (blockIdx.y == 2) ? s2 : s3;
    extern __shared__ char sm[];
    const unsigned sb = smem_u32(sm);
    const int tid  = threadIdx.x;
    const int wid  = tid >> 5;
    const int lane = tid & 31;
    const int wm   = wid & 3;
    const int wn   = wid >> 2;
    const int rowBase = blockIdx.x * 128;

    if (tid < 128) ((float*)(sm + NSM_BIAS))[tid] = s.bias[tid];

    #pragma unroll
    for (int u = 0; u < 8; u++) {
        const int g  = u * 256 + tid;
        const int r  = g >> 4, kc = g & 15;
        int R = rowBase + r; if (R >= M) R = M - 1;
        const int src = gidx ? gidx[R] : R;
        const float4 x0 = *(const float4*)(A + (long)src * DIM + kc * 8);
        const float4 x1 = *(const float4*)(A + (long)src * DIM + kc * 8 + 4);
        const float xs[8] = {x0.x, x0.y, x0.z, x0.w, x1.x, x1.y, x1.z, x1.w};
        const unsigned o = sw_off(r, kc);
        if (s.terms == 3) {
            uint4 H, L;
            split8(xs, H, L);
            *(uint4*)(sm + NSM_AHI + o) = H;
            *(uint4*)(sm + NSM_ALO + o) = L;
        } else {
            *(uint4*)(sm + NSM_AHI + o) = pack8bf(xs);
        }
    }
    stage_w(sm, NSM_WHI, NSM_WLO, s.wslot, tid);
    __syncthreads();

    float acc[2][8][4];
    if (s.terms == 3)
        mma_loop<3>(sb, NSM_AHI, NSM_ALO, NSM_WHI, NSM_WLO, wm, wn, lane, acc);
    else
        mma_loop<1>(sb, NSM_AHI, NSM_ALO, NSM_WHI, NSM_WLO, wm, wn, lane, acc);
    epi_f32(acc, (const float*)(sm + NSM_BIAS), s.C, rowBase, wm, wn, lane, M);
}

// ===========================================================================
// Item GEMM: single-term fp16 (output re-rounded to bf16 KV table)
// ===========================================================================
#define ISM_A    0u
#define ISM_W    32768u
#define ISM_BIAS 65536u
#define ISMEM    66048

__global__ void __launch_bounds__(256)
gemm_item(const float* __restrict__ A,
          const unsigned short* __restrict__ W0, const unsigned short* __restrict__ W1,
          const float* __restrict__ b0, const float* __restrict__ b1,
          __nv_bfloat16* __restrict__ KV, int M)
{
    const int y = blockIdx.y;
    const unsigned short* Wt = y ? W1 : W0;
    const float* bias = y ? b1 : b0;
    __nv_bfloat16* Cb = KV + (y ? 128 : 0);

    extern __shared__ char sm[];
    const unsigned sb = smem_u32(sm);
    const int tid  = threadIdx.x;
    const int wid  = tid >> 5;
    const int lane = tid & 31;
    const int wm   = wid & 3;
    const int wn   = wid >> 2;
    const int rowBase = blockIdx.x * 128;

    if (tid < 128) ((float*)(sm + ISM_BIAS))[tid] = bias[tid];

    #pragma unroll
    for (int u = 0; u < 8; u++) {
        const int g  = u * 256 + tid;
        const int r  = g >> 4, kc = g & 15;
        int R = rowBase + r; if (R >= M) R = M - 1;
        const float4 x0 = *(const float4*)(A + (long)R * DIM + kc * 8);
        const float4 x1 = *(const float4*)(A + (long)R * DIM + kc * 8 + 4);
        const float xs[8] = {x0.x, x0.y, x0.z, x0.w, x1.x, x1.y, x1.z, x1.w};
        *(uint4*)(sm + ISM_A + sw_off(r, kc)) = pack8f16(xs);
    }
    #pragma unroll
    for (int u = 0; u < 8; u++) {
        const int g  = u * 256 + tid;
        const int n  = g >> 4, kc = g & 15;
        *(uint4*)(sm + ISM_W + sw_off(n, kc)) = *(const uint4*)(Wt + n * DIM + kc * 8);
    }
    __syncthreads();

    float acc[2][8][4];
    #pragma unroll
    for (int i = 0; i < 2; i++)
        #pragma unroll
        for (int j = 0; j < 8; j++)
            #pragma unroll
            for (int q = 0; q < 4; q++) acc[i][j][q] = 0.f;

    #pragma unroll
    for (int ks = 0; ks < 8; ks++) {
        unsigned aH[2][4], bH[8][2];
        {
            const int r  = wm * 32 + (lane & 15);
            const int kc = ks * 2 + (lane >> 4);
            ldm4(aH[0][0], aH[0][1], aH[0][2], aH[0][3], sb + ISM_A + sw_off(r,      kc));
            ldm4(aH[1][0], aH[1][1], aH[1][2], aH[1][3], sb + ISM_A + sw_off(r + 16, kc));
        }
        {
            const int grp  = lane >> 3;
            const int nloc = (lane & 7) + ((grp >> 1) << 3);
            const int kc   = ks * 2 + (grp & 1);
            #pragma unroll
            for (int j = 0; j < 4; j++) {
                const int n = wn * 64 + j * 16 + nloc;
                ldm4(bH[2*j][0], bH[2*j][1], bH[2*j+1][0], bH[2*j+1][1],
                     sb + ISM_W + sw_off(n, kc));
            }
        }
        #pragma unroll
        for (int mf = 0; mf < 2; mf++)
            #pragma unroll
            for (int nf = 0; nf < 8; nf++)
                mma_f16(acc[mf][nf], aH[mf], bH[nf]);
    }

    const float* sbias = (const float*)(sm + ISM_BIAS);
    #pragma unroll
    for (int mf = 0; mf < 2; mf++) {
        const int r0 = rowBase + wm * 32 + mf * 16 + (lane >> 2);
        #pragma unroll
        for (int nf = 0; nf < 8; nf++) {
            const int c  = wn * 64 + nf * 8 + (lane & 3) * 2;
            const float b0v = sbias[c], b1v = sbias[c + 1];
            if (r0 < M) {
                const unsigned v = pack_bf2(fmaxf(acc[mf][nf][0] + b0v, 0.f),
                                            fmaxf(acc[mf][nf][1] + b1v, 0.f));
                *(unsigned*)(Cb + (long)r0 * 256 + c) = v;
            }
            if (r0 + 8 < M) {
                const unsigned v = pack_bf2(fmaxf(acc[mf][nf][2] + b0v, 0.f),
                                            fmaxf(acc[mf][nf][3] + b1v, 0.f));
                *(unsigned*)(Cb + (long)(r0 + 8) * 256 + c) = v;
            }
        }
    }
}

// ===========================================================================
// Fused chain: Agg = relu(Y@wo+bo) (kept in smem) -> K1 (1-term), V1 (3-term)
// ===========================================================================
#define CSM_AHI  0u
#define CSM_ALO  32768u
#define CSM_W1H  65536u
#define CSM_W1L  98304u
#define CSM_W2H  131072u
#define CSM_W2L  163840u
#define CSM_BIAS 196608u
#define CSMEM    198144

__global__ void __launch_bounds__(256)
agg_chain(const float* __restrict__ Y,
          const float* __restrict__ bo, const float* __restrict__ bk,
          const float* __restrict__ bv,
          float* __restrict__ K1, float* __restrict__ V1)
{
    extern __shared__ char sm[];
    const unsigned sb = smem_u32(sm);
    const int tid  = threadIdx.x;
    const int wid  = tid >> 5;
    const int lane = tid & 31;
    const int wm   = wid & 3;
    const int wn   = wid >> 2;
    const int rowBase = blockIdx.x * 128;

    if (tid < 128) {
        ((float*)(sm + CSM_BIAS))[tid]       = bo[tid];
        ((float*)(sm + CSM_BIAS + 512))[tid] = bk[tid];
        ((float*)(sm + CSM_BIAS + 1024))[tid]= bv[tid];
    }

    #pragma unroll
    for (int u = 0; u < 8; u++) {
        const int g  = u * 256 + tid;
        const int r  = g >> 4, kc = g & 15;
        const int R = rowBase + r;
        const float4 x0 = *(const float4*)(Y + (long)R * DIM + kc * 8);
        const float4 x1 = *(const float4*)(Y + (long)R * DIM + kc * 8 + 4);
        const float xs[8] = {x0.x, x0.y, x0.z, x0.w, x1.x, x1.y, x1.z, x1.w};
        uint4 H, L;
        split8(xs, H, L);
        const unsigned o = sw_off(r, kc);
        *(uint4*)(sm + CSM_AHI + o) = H;
        *(uint4*)(sm + CSM_ALO + o) = L;
    }
    stage_w(sm, CSM_W1H, CSM_W1L, 3, tid);   // gat_wo
    stage_w(sm, CSM_W2H, CSM_W2L, 5, tid);   // sem_wk
    __syncthreads();

    float acc[2][8][4];

    // phase 1: Agg = relu(Y@wo+bo), 3-term
    mma_loop<3>(sb, CSM_AHI, CSM_ALO, CSM_W1H, CSM_W1L, wm, wn, lane, acc);
    __syncthreads();

    // write Agg (bf16 hi/lo) back into the A buffers
    {
        const float* sbo = (const float*)(sm + CSM_BIAS);
        #pragma unroll
        for (int mf = 0; mf < 2; mf++) {
            const int r = wm * 32 + mf * 16 + (lane >> 2);
            #pragma unroll
            for (int nf = 0; nf < 8; nf++) {
                const int c  = wn * 64 + nf * 8 + (lane & 3) * 2;
                const float b0 = sbo[c], b1 = sbo[c + 1];
                const float v0 = fmaxf(acc[mf][nf][0] + b0, 0.f);
                const float v1 = fmaxf(acc[mf][nf][1] + b1, 0.f);
                const float v2 = fmaxf(acc[mf][nf][2] + b0, 0.f);
                const float v3 = fmaxf(acc[mf][nf][3] + b1, 0.f);
                const unsigned off0 = sw_off(r,     c >> 3) + (c & 7) * 2;
                const unsigned off1 = sw_off(r + 8, c >> 3) + (c & 7) * 2;
                *(unsigned*)(sm + CSM_AHI + off0) = pack_bf2(v0, v1);
                *(unsigned*)(sm + CSM_AHI + off1) = pack_bf2(v2, v3);
                *(unsigned*)(sm + CSM_ALO + off0) =
                    pack_bf2(v0 - bfhi(pack_bf2(0.f, v0)), v1 - bfhi(pack_bf2(0.f, v1)));
                *(unsigned*)(sm + CSM_ALO + off1) =
                    pack_bf2(v2 - bfhi(pack_bf2(0.f, v2)), v3 - bfhi(pack_bf2(0.f, v3)));
            }
        }
    }
    stage_w(sm, CSM_W1H, CSM_W1L, 6, tid);   // sem_wv
    __syncthreads();

    // phase 2: K1 = relu(Agg@wk+bk) — score path, 1-term
    mma_loop<1>(sb, CSM_AHI, CSM_ALO, CSM_W2H, CSM_W2L, wm, wn, lane, acc);
    epi_f32(acc, (const float*)(sm + CSM_BIAS + 512), K1, rowBase, wm, wn, lane, BATCH);

    // phase 3: V1 = relu(Agg@wv+bv) — value path, 3-term
    mma_loop<3>(sb, CSM_AHI, CSM_ALO, CSM_W1H, CSM_W1L, wm, wn, lane, acc);
    epi_f32(acc, (const float*)(sm + CSM_BIAS + 1024), V1, rowBase, wm, wn, lane, BATCH);
}

// ===========================================================================
// Fused sem attention + final projection (3-term)
// ===========================================================================
__global__ void __launch_bounds__(256)
sem_final(const float* __restrict__ Q2, const float* __restrict__ K0,
          const float* __restrict__ K1, const float* __restrict__ V0,
          const float* __restrict__ V1, const float* __restrict__ bo2,
          float* __restrict__ out)
{
    extern __shared__ char sm[];
    const unsigned sb = smem_u32(sm);
    const int tid  = threadIdx.x;
    const int wid  = tid >> 5;
    const int lane = tid & 31;
    const int wm   = wid & 3;
    const int wn   = wid >> 2;
    const int rowBase = blockIdx.x * 128;

    if (tid < 128) ((float*)(sm + NSM_BIAS))[tid] = bo2[tid];

    const float scale = 0.08838834764831845f;
    #pragma unroll
    for (int u = 0; u < 8; u++) {
        const int g  = u * 256 + tid;
        const int r  = g >> 4, kc = g & 15;
        const long base = (long)(rowBase + r) * DIM + kc * 8;

        const float4 qa = *(const float4*)(Q2 + base);
        const float4 qb = *(const float4*)(Q2 + base + 4);
        const float4 k0a = *(const float4*)(K0 + base);
        const float4 k0b = *(const float4*)(K0 + base + 4);
        const float4 k1a = *(const float4*)(K1 + base);
        const float4 k1b = *(const float4*)(K1 + base + 4);

        float s0 = qa.x*k0a.x + qa.y*k0a.y + qa.z*k0a.z + qa.w*k0a.w
                 + qb.x*k0b.x + qb.y*k0b.y + qb.z*k0b.z + qb.w*k0b.w;
        float s1 = qa.x*k1a.x + qa.y*k1a.y + qa.z*k1a.z + qa.w*k1a.w
                 + qb.x*k1b.x + qb.y*k1b.y + qb.z*k1b.z + qb.w*k1b.w;
        #pragma unroll
        for (int o = 8; o; o >>= 1) {
            s0 += __shfl_xor_sync(0xffffffffu, s0, o);
            s1 += __shfl_xor_sync(0xffffffffu, s1, o);
        }
        s0 *= scale; s1 *= scale;
        const float m  = fmaxf(s0, s1);
        const float e0 = __expf(s0 - m);
        const float e1 = __expf(s1 - m);
        const float inv = 1.0f / (e0 + e1);
        const float p0 = e0 * inv, p1 = e1 * inv;

        const float4 v0a = *(const float4*)(V0 + base);
        const float4 v0b = *(const float4*)(V0 + base + 4);
        const float4 v1a = *(const float4*)(V1 + base);
        const float4 v1b = *(const float4*)(V1 + base + 4);
        const float xs[8] = {
            p0*v0a.x + p1*v1a.x, p0*v0a.y + p1*v1a.y,
            p0*v0a.z + p1*v1a.z, p0*v0a.w + p1*v1a.w,
            p0*v0b.x + p1*v1b.x, p0*v0b.y + p1*v1b.y,
            p0*v0b.z + p1*v1b.z, p0*v0b.w + p1*v1b.w };
        uint4 H, L;
        split8(xs, H, L);
        const unsigned o = sw_off(r, kc);
        *(uint4*)(sm + NSM_AHI + o) = H;
        *(uint4*)(sm + NSM_ALO + o) = L;
    }
    stage_w(sm, NSM_WHI, NSM_WLO, 7, tid);   // sem_wo
    __syncthreads();

    float acc[2][8][4];
    mma_loop<3>(sb, NSM_AHI, NSM_ALO, NSM_WHI, NSM_WLO, wm, wn, lane, acc);
    epi_f32(acc, (const float*)(sm + NSM_BIAS), out, rowBase, wm, wn, lane, BATCH);
}

// ---------------------------------------------------------------------------
// GAT attention v3: paired-item 16B loads, byte-offset indices, no max-sub.
// ---------------------------------------------------------------------------
__global__ void __launch_bounds__(256)
gat_attn(const float* __restrict__ Q, const int* __restrict__ movies,
         const __nv_bfloat16* __restrict__ KV, float* __restrict__ Y)
{
    const int w    = threadIdx.x >> 5;
    const int lane = threadIdx.x & 31;
    const int half = lane >> 4;
    const int cl   = lane & 15;
    const int b    = blockIdx.x * 8 + w;
    const char* KVc = (const char*)KV;

    __shared__ int   sidx[8][NHIST];     // byte offsets (item * 512)
    __shared__ float sp  [8][NHIST];

    if (lane < NHIST)      sidx[w][lane]      = movies[(b * NHIST + lane) * 2] << 9;
    if (lane + 32 < NHIST) sidx[w][lane + 32] = movies[(b * NHIST + lane + 32) * 2] << 9;
    __syncwarp();

    const float4 qa = *(const float4*)(Q + (long)b * DIM + cl * 8);
    const float4 qb = *(const float4*)(Q + (long)b * DIM + cl * 8 + 4);

    // ---- scores ------------------------------------------------------------
    #pragma unroll
    for (int t0 = 0; t0 < 25; t0 += 5) {
        uint4 kr[5];
        #pragma unroll
        for (int j = 0; j < 5; j++)
            kr[j] = *(const uint4*)(KVc + sidx[w][2*(t0+j) + half] + cl * 16);
        float sc[5];
        #pragma unroll
        for (int j = 0; j < 5; j++) {
            float s;
            s  = qa.x * bflo(kr[j].x) + qa.y * bfhi(kr[j].x);
            s += qa.z * bflo(kr[j].y) + qa.w * bfhi(kr[j].y);
            s += qb.x * bflo(kr[j].z) + qb.y * bfhi(kr[j].z);
            s += qb.z * bflo(kr[j].w) + qb.w * bfhi(kr[j].w);
            sc[j] = s;
        }
        #pragma unroll
        for (int j = 0; j < 5; j++)
            #pragma unroll
            for (int off = 8; off; off >>= 1)
                sc[j] += __shfl_xor_sync(0xffffffffu, sc[j], off);
        if (cl == 0) {
            #pragma unroll
            for (int j = 0; j < 5; j++) sp[w][2*(t0+j) + half] = sc[j];
        }
    }
    __syncwarp();

    // ---- softmax over 50 (no max subtraction: scores are O(1) bounded) ------
    const float scale = 0.08838834764831845f;
    float e0 = (lane < NHIST)      ? __expf(sp[w][lane]      * scale) : 0.f;
    float e1 = (lane + 32 < NHIST) ? __expf(sp[w][lane + 32] * scale) : 0.f;
    float es = e0 + e1;
    #pragma unroll
    for (int off = 16; off; off >>= 1)
        es += __shfl_xor_sync(0xffffffffu, es, off);
    const float inv = 1.0f / es;
    if (lane < NHIST)      sp[w][lane]      = e0 * inv;
    if (lane + 32 < NHIST) sp[w][lane + 32] = e1 * inv;
    __syncwarp();

    // ---- weighted V sum ------------------------------------------------------
    float acc[8];
    #pragma unroll
    for (int i = 0; i < 8; i++) acc[i] = 0.f;

    #pragma unroll
    for (int t0 = 0; t0 < 25; t0 += 5) {
        uint4 vr[5];
        float pj[5];
        #pragma unroll
        for (int j = 0; j < 5; j++) {
            vr[j] = *(const uint4*)(KVc + sidx[w][2*(t0+j) + half] + 256 + cl * 16);
            pj[j] = sp[w][2*(t0+j) + half];
        }
        #pragma unroll
        for (int j = 0; j < 5; j++) {
            acc[0] = fmaf(pj[j], bflo(vr[j].x), acc[0]);
            acc[1] = fmaf(pj[j], bfhi(vr[j].x), acc[1]);
            acc[2] = fmaf(pj[j], bflo(vr[j].y), acc[2]);
            acc[3] = fmaf(pj[j], bfhi(vr[j].y), acc[3]);
            acc[4] = fmaf(pj[j], bflo(vr[j].z), acc[4]);
            acc[5] = fmaf(pj[j], bfhi(vr[j].z), acc[5]);
            acc[6] = fmaf(pj[j], bflo(vr[j].w), acc[6]);
            acc[7] = fmaf(pj[j], bfhi(vr[j].w), acc[7]);
        }
    }
    #pragma unroll
    for (int i = 0; i < 8; i++)
        acc[i] += __shfl_xor_sync(0xffffffffu, acc[i], 16);

    if (half == 0) {
        *(float4*)(Y + (long)b * DIM + cl * 8)     = make_float4(acc[0], acc[1], acc[2], acc[3]);
        *(float4*)(Y + (long)b * DIM + cl * 8 + 4) = make_float4(acc[4], acc[5], acc[6], acc[7]);
    }
}

// ---------------------------------------------------------------------------
// Host launcher (6 launches)
// ---------------------------------------------------------------------------
extern "C" void kernel_launch(void* const* d_in, const int* in_sizes, int n_in,
                              void* d_out, int out_size)
{
    const int*   uids       = (const int*)  d_in[0];
    const int*   u_movies   = (const int*)  d_in[2];
    const float* user_table = (const float*)d_in[3];
    const float* item_table = (const float*)d_in[5];
    const float* gat_wq = (const float*)d_in[6],  *gat_bq = (const float*)d_in[7];
    const float* gat_wk = (const float*)d_in[8],  *gat_bk = (const float*)d_in[9];
    const float* gat_wv = (const float*)d_in[10], *gat_bv = (const float*)d_in[11];
    const float* gat_wo = (const float*)d_in[12], *gat_bo = (const float*)d_in[13];
    const float* sem_wq = (const float*)d_in[14], *sem_bq = (const float*)d_in[15];
    const float* sem_wk = (const float*)d_in[16], *sem_bk = (const float*)d_in[17];
    const float* sem_wv = (const float*)d_in[18], *sem_bv = (const float*)d_in[19];
    const float* sem_wo = (const float*)d_in[20], *sem_bo = (const float*)d_in[21];
    float* out = (float*)d_out;

    __nv_bfloat16* KV;
    unsigned short *Wh0, *Wh1;
    float *Qg, *Q2, *K0, *V0, *K1, *V1, *Y;
    cudaGetSymbolAddress((void**)&KV,  g_KV);
    cudaGetSymbolAddress((void**)&Qg,  g_Qg);
    cudaGetSymbolAddress((void**)&Q2,  g_Q2);
    cudaGetSymbolAddress((void**)&K0,  g_K0);
    cudaGetSymbolAddress((void**)&V0,  g_V0);
    cudaGetSymbolAddress((void**)&K1,  g_K1);
    cudaGetSymbolAddress((void**)&V1,  g_V1);
    cudaGetSymbolAddress((void**)&Y,   g_Y);
    {
        void* p;
        cudaGetSymbolAddress(&p, g_Wh);
        Wh0 = (unsigned short*)p;
        Wh1 = Wh0 + DIM * DIM;
    }

    static bool attr_done = false;
    if (!attr_done) {
        cudaFuncSetAttribute(gemm_hmma, cudaFuncAttributeMaxDynamicSharedMemorySize, NSMEM);
        cudaFuncSetAttribute(gemm_item, cudaFuncAttributeMaxDynamicSharedMemorySize, ISMEM);
        cudaFuncSetAttribute(agg_chain, cudaFuncAttributeMaxDynamicSharedMemorySize, CSMEM);
        cudaFuncSetAttribute(sem_final, cudaFuncAttributeMaxDynamicSharedMemorySize, NSMEM);
        attr_done = true;
    }

    const dim3 blk(256);
    const int gItems = (NITEMS + 127) / 128;     // 782
    const int gBatch = BATCH / 128;              // 128

    // score-path outputs (Qg, Q2, K0) -> 1-term; value-path (V0) -> 3-term
    HSet sQg = { 0, gat_bq, Qg, 1 };
    HSet sQ2 = { 4, sem_bq, Q2, 1 };
    HSet sK0 = { 5, sem_bk, K0, 1 };
    HSet sV0 = { 6, sem_bv, V0, 3 };

    // 0: weight transpose + splits
    w_setup<<<64, 256>>>(gat_wq, gat_wk, gat_wv, gat_wo,
                         sem_wq, sem_wk, sem_wv, sem_wo);

    // 1: item K/V -> bf16 KV table (single-term fp16)
    gemm_item<<<dim3(gItems, 2), blk, ISMEM>>>(item_table, Wh0, Wh1,
                                               gat_bk, gat_bv, KV, NITEMS);

    // 2: node transforms (mixed terms)
    gemm_hmma<<<dim3(gBatch, 4), blk, NSMEM>>>(user_table, uids,
                                               sQg, sQ2, sK0, sV0, BATCH);

    // 3: GAT attention
    gat_attn<<<BATCH / 8, blk>>>(Qg, u_movies, KV, Y);

    // 4: fused Agg -> K1 (1-term), V1 (3-term)
    agg_chain<<<gBatch, blk, CSMEM>>>(Y, gat_bo, sem_bk, sem_bv, K1, V1);

    // 5: fused sem attention + final projection into d_out
    sem_final<<<gBatch, blk, NSMEM>>>(Q2, K0, K1, V0, V1, sem_bo, out);
}

// round 10
// speedup vs baseline: 1.1254x; 1.1254x over previous
#include <cuda_runtime.h>
#include <cuda_bf16.h>
#include <cuda_fp16.h>
#include <math.h>

// ---------------------------------------------------------------------------
// Problem constants
// ---------------------------------------------------------------------------
#define BATCH   16384
#define NHIST   50
#define DIM     128
#define NITEMS  100000

// ---------------------------------------------------------------------------
// Scratch (static device globals)
// ---------------------------------------------------------------------------
__device__ __nv_bfloat16 g_KV[NITEMS * 256];   // per item: 128 bf16 K | 128 bf16 V
__device__ float g_Qg [BATCH * DIM];
__device__ float g_Q2 [BATCH * DIM];
__device__ float g_K0 [BATCH * DIM];
__device__ float g_V0 [BATCH * DIM];
__device__ float g_K1 [BATCH * DIM];
__device__ float g_V1 [BATCH * DIM];
__device__ float g_Y  [BATCH * DIM];
// bf16 weight splits, transposed to [n][k]: slot 2*w = hi, 2*w+1 = lo
// w: 0=gat_wq 1=gat_wk 2=gat_wv 3=gat_wo 4=sem_wq 5=sem_wk 6=sem_wv 7=sem_wo
__device__ unsigned short g_W4[16][DIM * DIM];
// fp16 transposed weights for the item GEMM: 0=gat_wk, 1=gat_wv
__device__ unsigned short g_Wh[2][DIM * DIM];

// ---------------------------------------------------------------------------
// helpers
// ---------------------------------------------------------------------------
__device__ __forceinline__ unsigned smem_u32(const void* p) {
    unsigned a;
    asm("{ .reg .u64 t; cvta.to.shared.u64 t, %1; cvt.u32.u64 %0, t; }"
        : "=r"(a) : "l"(p));
    return a;
}
__device__ __forceinline__ void ldm4(unsigned& r0, unsigned& r1,
                                     unsigned& r2, unsigned& r3, unsigned addr) {
    asm volatile("ldmatrix.sync.aligned.m8n8.x4.shared.b16 {%0,%1,%2,%3}, [%4];"
                 : "=r"(r0), "=r"(r1), "=r"(r2), "=r"(r3) : "r"(addr));
}
__device__ __forceinline__ void mma_bf16(float* d, const unsigned* a, const unsigned* b) {
    asm volatile("mma.sync.aligned.m16n8k16.row.col.f32.bf16.bf16.f32 "
                 "{%0,%1,%2,%3}, {%4,%5,%6,%7}, {%8,%9}, {%0,%1,%2,%3};"
                 : "+f"(d[0]), "+f"(d[1]), "+f"(d[2]), "+f"(d[3])
                 : "r"(a[0]), "r"(a[1]), "r"(a[2]), "r"(a[3]),
                   "r"(b[0]), "r"(b[1]));
}
__device__ __forceinline__ void mma_f16(float* d, const unsigned* a, const unsigned* b) {
    asm volatile("mma.sync.aligned.m16n8k16.row.col.f32.f16.f16.f32 "
                 "{%0,%1,%2,%3}, {%4,%5,%6,%7}, {%8,%9}, {%0,%1,%2,%3};"
                 : "+f"(d[0]), "+f"(d[1]), "+f"(d[2]), "+f"(d[3])
                 : "r"(a[0]), "r"(a[1]), "r"(a[2]), "r"(a[3]),
                   "r"(b[0]), "r"(b[1]));
}
// smem byte offset for (row, 8-elem 16B chunk kc): 256B rows, XOR swizzle
__device__ __forceinline__ unsigned sw_off(int row, int kc) {
    return (unsigned)(row * 256 + ((kc ^ (row & 7)) << 4));
}
// split 8 fp32 -> two uint4 of bf16 (hi, lo = residual)
__device__ __forceinline__ void split8(const float* xs, uint4& H, uint4& L) {
    unsigned hw[4], lw[4];
    #pragma unroll
    for (int j = 0; j < 4; j++) {
        __nv_bfloat16 h0 = __float2bfloat16(xs[2*j]);
        __nv_bfloat16 h1 = __float2bfloat16(xs[2*j+1]);
        __nv_bfloat16 l0 = __float2bfloat16(xs[2*j]   - __bfloat162float(h0));
        __nv_bfloat16 l1 = __float2bfloat16(xs[2*j+1] - __bfloat162float(h1));
        hw[j] = (unsigned)*(unsigned short*)&h0 | ((unsigned)*(unsigned short*)&h1 << 16);
        lw[j] = (unsigned)*(unsigned short*)&l0 | ((unsigned)*(unsigned short*)&l1 << 16);
    }
    H = make_uint4(hw[0], hw[1], hw[2], hw[3]);
    L = make_uint4(lw[0], lw[1], lw[2], lw[3]);
}
// 8 fp32 -> uint4 of fp16
__device__ __forceinline__ uint4 pack8f16(const float* xs) {
    unsigned hw[4];
    #pragma unroll
    for (int j = 0; j < 4; j++) {
        const unsigned short a = __half_as_ushort(__float2half_rn(xs[2*j]));
        const unsigned short b = __half_as_ushort(__float2half_rn(xs[2*j+1]));
        hw[j] = (unsigned)a | ((unsigned)b << 16);
    }
    return make_uint4(hw[0], hw[1], hw[2], hw[3]);
}
__device__ __forceinline__ unsigned pack_bf2(float a, float b) {
    __nv_bfloat16 x = __float2bfloat16(a), y = __float2bfloat16(b);
    return (unsigned)*(unsigned short*)&x | ((unsigned)*(unsigned short*)&y << 16);
}
// bf16x2 unpack via shift/mask
__device__ __forceinline__ float bflo(unsigned u) { return __uint_as_float(u << 16); }
__device__ __forceinline__ float bfhi(unsigned u) { return __uint_as_float(u & 0xffff0000u); }

// ===========================================================================
// Setup: transpose + split all weight matrices
// ===========================================================================
__global__ void w_setup(const float* w0, const float* w1, const float* w2,
                        const float* w3, const float* w4, const float* w5,
                        const float* w6, const float* w7)
{
    const int i = blockIdx.x * blockDim.x + threadIdx.x;
    if (i >= DIM * DIM) return;
    const float* ws[8] = {w0, w1, w2, w3, w4, w5, w6, w7};
    const int k = i >> 7, n = i & 127;
    const int dst = n * DIM + k;
    #pragma unroll
    for (int w = 0; w < 8; w++) {
        const float a = ws[w][i];
        __nv_bfloat16 h = __float2bfloat16(a);
        __nv_bfloat16 l = __float2bfloat16(a - __bfloat162float(h));
        g_W4[2*w    ][dst] = *(unsigned short*)&h;
        g_W4[2*w + 1][dst] = *(unsigned short*)&l;
    }
    g_Wh[0][dst] = __half_as_ushort(__float2half_rn(w1[i]));   // gat_wk
    g_Wh[1][dst] = __half_as_ushort(__float2half_rn(w2[i]));   // gat_wv
}

// ===========================================================================
// Shared GEMM building blocks. 8 warps (4x2), warp tile 32x64, CTA 128x128.
// TERMS=3: D = Ah*Wh + Ah*Wl + Al*Wh.  TERMS=1: D = Ah*Wh (score path).
// ===========================================================================
template<int TERMS>
__device__ __forceinline__ void mma_loop(
    unsigned sb, unsigned oAhi, unsigned oAlo, unsigned oWhi, unsigned oWlo,
    int wm, int wn, int lane, float acc[2][8][4])
{
    #pragma unroll
    for (int i = 0; i < 2; i++)
        #pragma unroll
        for (int j = 0; j < 8; j++)
            #pragma unroll
            for (int q = 0; q < 4; q++) acc[i][j][q] = 0.f;

    #pragma unroll
    for (int ks = 0; ks < 8; ks++) {
        unsigned aH[2][4], aL[2][4], bH[8][2], bL[8][2];
        {
            const int r  = wm * 32 + (lane & 15);
            const int kc = ks * 2 + (lane >> 4);
            ldm4(aH[0][0], aH[0][1], aH[0][2], aH[0][3], sb + oAhi + sw_off(r,      kc));
            ldm4(aH[1][0], aH[1][1], aH[1][2], aH[1][3], sb + oAhi + sw_off(r + 16, kc));
            if (TERMS == 3) {
                ldm4(aL[0][0], aL[0][1], aL[0][2], aL[0][3], sb + oAlo + sw_off(r,      kc));
                ldm4(aL[1][0], aL[1][1], aL[1][2], aL[1][3], sb + oAlo + sw_off(r + 16, kc));
            }
        }
        {
            const int grp  = lane >> 3;
            const int nloc = (lane & 7) + ((grp >> 1) << 3);
            const int kc   = ks * 2 + (grp & 1);
            #pragma unroll
            for (int j = 0; j < 4; j++) {
                const int n = wn * 64 + j * 16 + nloc;
                ldm4(bH[2*j][0], bH[2*j][1], bH[2*j+1][0], bH[2*j+1][1],
                     sb + oWhi + sw_off(n, kc));
                if (TERMS == 3)
                    ldm4(bL[2*j][0], bL[2*j][1], bL[2*j+1][0], bL[2*j+1][1],
                         sb + oWlo + sw_off(n, kc));
            }
        }
        #pragma unroll
        for (int mf = 0; mf < 2; mf++)
            #pragma unroll
            for (int nf = 0; nf < 8; nf++) {
                mma_bf16(acc[mf][nf], aH[mf], bH[nf]);
                if (TERMS == 3) {
                    mma_bf16(acc[mf][nf], aH[mf], bL[nf]);
                    mma_bf16(acc[mf][nf], aL[mf], bH[nf]);
                }
            }
    }
}

__device__ __forceinline__ void epi_f32(
    float acc[2][8][4], const float* sbias, float* C,
    int rowBase, int wm, int wn, int lane, int M)
{
    #pragma unroll
    for (int mf = 0; mf < 2; mf++) {
        const int r0 = rowBase + wm * 32 + mf * 16 + (lane >> 2);
        #pragma unroll
        for (int nf = 0; nf < 8; nf++) {
            const int c  = wn * 64 + nf * 8 + (lane & 3) * 2;
            const float b0 = sbias[c], b1 = sbias[c + 1];
            if (r0 < M)
                *(float2*)(C + (long)r0 * DIM + c) =
                    make_float2(fmaxf(acc[mf][nf][0] + b0, 0.f),
                                fmaxf(acc[mf][nf][1] + b1, 0.f));
            if (r0 + 8 < M)
                *(float2*)(C + (long)(r0 + 8) * DIM + c) =
                    make_float2(fmaxf(acc[mf][nf][2] + b0, 0.f),
                                fmaxf(acc[mf][nf][3] + b1, 0.f));
        }
    }
}

__device__ __forceinline__ void stage_w(
    char* sm, unsigned oWhi, unsigned oWlo, int wslot, int tid)
{
    const unsigned short* WH = g_W4[2 * wslot];
    const unsigned short* WL = g_W4[2 * wslot + 1];
    #pragma unroll
    for (int u = 0; u < 8; u++) {
        const int g  = u * 256 + tid;
        const int n  = g >> 4, kc = g & 15;
        const unsigned o = sw_off(n, kc);
        *(uint4*)(sm + oWhi + o) = *(const uint4*)(WH + n * DIM + kc * 8);
        *(uint4*)(sm + oWlo + o) = *(const uint4*)(WL + n * DIM + kc * 8);
    }
}

// ===========================================================================
// Fused node transforms: stage gathered A ONCE, then 4 phases
// (Qg 1-term, Q2 1-term, K0 1-term, V0 3-term) with W re-staged per phase.
// smem: A-hi 32K | A-lo 32K | W-hi 32K | W-lo 32K | 4 biases (2K)
// ===========================================================================
#define NSM_AHI  0u
#define NSM_ALO  32768u
#define NSM_WHI  65536u
#define NSM_WLO  98304u
#define NSM_BIAS 131072u
#define NSMEM    133120

__global__ void __launch_bounds__(256)
node_all(const float* __restrict__ A, const int* __restrict__ gidx,
         const float* __restrict__ bq, const float* __restrict__ bq2,
         const float* __restrict__ bk, const float* __restrict__ bv,
         float* __restrict__ Qg, float* __restrict__ Q2,
         float* __restrict__ K0, float* __restrict__ V0)
{
    extern __shared__ char sm[];
    const unsigned sb = smem_u32(sm);
    const int tid  = threadIdx.x;
    const int wid  = tid >> 5;
    const int lane = tid & 31;
    const int wm   = wid & 3;
    const int wn   = wid >> 2;
    const int rowBase = blockIdx.x * 128;

    if (tid < 128) {
        ((float*)(sm + NSM_BIAS))[tid]        = bq[tid];
        ((float*)(sm + NSM_BIAS + 512))[tid]  = bq2[tid];
        ((float*)(sm + NSM_BIAS + 1024))[tid] = bk[tid];
        ((float*)(sm + NSM_BIAS + 1536))[tid] = bv[tid];
    }

    // --- A staging ONCE: gather + bf16 hi/lo split, swizzled ---------------
    #pragma unroll
    for (int u = 0; u < 8; u++) {
        const int g  = u * 256 + tid;
        const int r  = g >> 4, kc = g & 15;
        const int src = gidx[rowBase + r];
        const float4 x0 = *(const float4*)(A + (long)src * DIM + kc * 8);
        const float4 x1 = *(const float4*)(A + (long)src * DIM + kc * 8 + 4);
        const float xs[8] = {x0.x, x0.y, x0.z, x0.w, x1.x, x1.y, x1.z, x1.w};
        uint4 H, L;
        split8(xs, H, L);
        const unsigned o = sw_off(r, kc);
        *(uint4*)(sm + NSM_AHI + o) = H;
        *(uint4*)(sm + NSM_ALO + o) = L;
    }
    stage_w(sm, NSM_WHI, NSM_WLO, 0, tid);   // gat_wq
    __syncthreads();

    float acc[2][8][4];

    // phase 1: Qg (score path, 1-term)
    mma_loop<1>(sb, NSM_AHI, NSM_ALO, NSM_WHI, NSM_WLO, wm, wn, lane, acc);
    __syncthreads();
    stage_w(sm, NSM_WHI, NSM_WLO, 4, tid);   // sem_wq
    epi_f32(acc, (const float*)(sm + NSM_BIAS), Qg, rowBase, wm, wn, lane, BATCH);
    __syncthreads();

    // phase 2: Q2 (score path, 1-term)
    mma_loop<1>(sb, NSM_AHI, NSM_ALO, NSM_WHI, NSM_WLO, wm, wn, lane, acc);
    __syncthreads();
    stage_w(sm, NSM_WHI, NSM_WLO, 5, tid);   // sem_wk
    epi_f32(acc, (const float*)(sm + NSM_BIAS + 512), Q2, rowBase, wm, wn, lane, BATCH);
    __syncthreads();

    // phase 3: K0 (score path, 1-term)
    mma_loop<1>(sb, NSM_AHI, NSM_ALO, NSM_WHI, NSM_WLO, wm, wn, lane, acc);
    __syncthreads();
    stage_w(sm, NSM_WHI, NSM_WLO, 6, tid);   // sem_wv
    epi_f32(acc, (const float*)(sm + NSM_BIAS + 1024), K0, rowBase, wm, wn, lane, BATCH);
    __syncthreads();

    // phase 4: V0 (value path, 3-term)
    mma_loop<3>(sb, NSM_AHI, NSM_ALO, NSM_WHI, NSM_WLO, wm, wn, lane, acc);
    epi_f32(acc, (const float*)(sm + NSM_BIAS + 1536), V0, rowBase, wm, wn, lane, BATCH);
}

// ===========================================================================
// Item GEMM: single-term fp16 (output re-rounded to bf16 KV table)
// ===========================================================================
#define ISM_A    0u
#define ISM_W    32768u
#define ISM_BIAS 65536u
#define ISMEM    66048

__global__ void __launch_bounds__(256)
gemm_item(const float* __restrict__ A,
          const unsigned short* __restrict__ W0, const unsigned short* __restrict__ W1,
          const float* __restrict__ b0, const float* __restrict__ b1,
          __nv_bfloat16* __restrict__ KV, int M)
{
    const int y = blockIdx.y;
    const unsigned short* Wt = y ? W1 : W0;
    const float* bias = y ? b1 : b0;
    __nv_bfloat16* Cb = KV + (y ? 128 : 0);

    extern __shared__ char sm[];
    const unsigned sb = smem_u32(sm);
    const int tid  = threadIdx.x;
    const int wid  = tid >> 5;
    const int lane = tid & 31;
    const int wm   = wid & 3;
    const int wn   = wid >> 2;
    const int rowBase = blockIdx.x * 128;

    if (tid < 128) ((float*)(sm + ISM_BIAS))[tid] = bias[tid];

    #pragma unroll
    for (int u = 0; u < 8; u++) {
        const int g  = u * 256 + tid;
        const int r  = g >> 4, kc = g & 15;
        int R = rowBase + r; if (R >= M) R = M - 1;
        const float4 x0 = *(const float4*)(A + (long)R * DIM + kc * 8);
        const float4 x1 = *(const float4*)(A + (long)R * DIM + kc * 8 + 4);
        const float xs[8] = {x0.x, x0.y, x0.z, x0.w, x1.x, x1.y, x1.z, x1.w};
        *(uint4*)(sm + ISM_A + sw_off(r, kc)) = pack8f16(xs);
    }
    #pragma unroll
    for (int u = 0; u < 8; u++) {
        const int g  = u * 256 + tid;
        const int n  = g >> 4, kc = g & 15;
        *(uint4*)(sm + ISM_W + sw_off(n, kc)) = *(const uint4*)(Wt + n * DIM + kc * 8);
    }
    __syncthreads();

    float acc[2][8][4];
    #pragma unroll
    for (int i = 0; i < 2; i++)
        #pragma unroll
        for (int j = 0; j < 8; j++)
            #pragma unroll
            for (int q = 0; q < 4; q++) acc[i][j][q] = 0.f;

    #pragma unroll
    for (int ks = 0; ks < 8; ks++) {
        unsigned aH[2][4], bH[8][2];
        {
            const int r  = wm * 32 + (lane & 15);
            const int kc = ks * 2 + (lane >> 4);
            ldm4(aH[0][0], aH[0][1], aH[0][2], aH[0][3], sb + ISM_A + sw_off(r,      kc));
            ldm4(aH[1][0], aH[1][1], aH[1][2], aH[1][3], sb + ISM_A + sw_off(r + 16, kc));
        }
        {
            const int grp  = lane >> 3;
            const int nloc = (lane & 7) + ((grp >> 1) << 3);
            const int kc   = ks * 2 + (grp & 1);
            #pragma unroll
            for (int j = 0; j < 4; j++) {
                const int n = wn * 64 + j * 16 + nloc;
                ldm4(bH[2*j][0], bH[2*j][1], bH[2*j+1][0], bH[2*j+1][1],
                     sb + ISM_W + sw_off(n, kc));
            }
        }
        #pragma unroll
        for (int mf = 0; mf < 2; mf++)
            #pragma unroll
            for (int nf = 0; nf < 8; nf++)
                mma_f16(acc[mf][nf], aH[mf], bH[nf]);
    }

    const float* sbias = (const float*)(sm + ISM_BIAS);
    #pragma unroll
    for (int mf = 0; mf < 2; mf++) {
        const int r0 = rowBase + wm * 32 + mf * 16 + (lane >> 2);
        #pragma unroll
        for (int nf = 0; nf < 8; nf++) {
            const int c  = wn * 64 + nf * 8 + (lane & 3) * 2;
            const float b0v = sbias[c], b1v = sbias[c + 1];
            if (r0 < M) {
                const unsigned v = pack_bf2(fmaxf(acc[mf][nf][0] + b0v, 0.f),
                                            fmaxf(acc[mf][nf][1] + b1v, 0.f));
                *(unsigned*)(Cb + (long)r0 * 256 + c) = v;
            }
            if (r0 + 8 < M) {
                const unsigned v = pack_bf2(fmaxf(acc[mf][nf][2] + b0v, 0.f),
                                            fmaxf(acc[mf][nf][3] + b1v, 0.f));
                *(unsigned*)(Cb + (long)(r0 + 8) * 256 + c) = v;
            }
        }
    }
}

// ===========================================================================
// Fused chain: Agg = relu(Y@wo+bo) (kept in smem) -> K1 (1-term), V1 (3-term)
// ===========================================================================
#define CSM_AHI  0u
#define CSM_ALO  32768u
#define CSM_W1H  65536u
#define CSM_W1L  98304u
#define CSM_W2H  131072u
#define CSM_W2L  163840u
#define CSM_BIAS 196608u
#define CSMEM    198144

__global__ void __launch_bounds__(256)
agg_chain(const float* __restrict__ Y,
          const float* __restrict__ bo, const float* __restrict__ bk,
          const float* __restrict__ bv,
          float* __restrict__ K1, float* __restrict__ V1)
{
    extern __shared__ char sm[];
    const unsigned sb = smem_u32(sm);
    const int tid  = threadIdx.x;
    const int wid  = tid >> 5;
    const int lane = tid & 31;
    const int wm   = wid & 3;
    const int wn   = wid >> 2;
    const int rowBase = blockIdx.x * 128;

    if (tid < 128) {
        ((float*)(sm + CSM_BIAS))[tid]       = bo[tid];
        ((float*)(sm + CSM_BIAS + 512))[tid] = bk[tid];
        ((float*)(sm + CSM_BIAS + 1024))[tid]= bv[tid];
    }

    #pragma unroll
    for (int u = 0; u < 8; u++) {
        const int g  = u * 256 + tid;
        const int r  = g >> 4, kc = g & 15;
        const int R = rowBase + r;
        const float4 x0 = *(const float4*)(Y + (long)R * DIM + kc * 8);
        const float4 x1 = *(const float4*)(Y + (long)R * DIM + kc * 8 + 4);
        const float xs[8] = {x0.x, x0.y, x0.z, x0.w, x1.x, x1.y, x1.z, x1.w};
        uint4 H, L;
        split8(xs, H, L);
        const unsigned o = sw_off(r, kc);
        *(uint4*)(sm + CSM_AHI + o) = H;
        *(uint4*)(sm + CSM_ALO + o) = L;
    }
    stage_w(sm, CSM_W1H, CSM_W1L, 3, tid);   // gat_wo
    stage_w(sm, CSM_W2H, CSM_W2L, 5, tid);   // sem_wk
    __syncthreads();

    float acc[2][8][4];

    // phase 1: Agg = relu(Y@wo+bo), 3-term
    mma_loop<3>(sb, CSM_AHI, CSM_ALO, CSM_W1H, CSM_W1L, wm, wn, lane, acc);
    __syncthreads();

    // write Agg (bf16 hi/lo) back into the A buffers
    {
        const float* sbo = (const float*)(sm + CSM_BIAS);
        #pragma unroll
        for (int mf = 0; mf < 2; mf++) {
            const int r = wm * 32 + mf * 16 + (lane >> 2);
            #pragma unroll
            for (int nf = 0; nf < 8; nf++) {
                const int c  = wn * 64 + nf * 8 + (lane & 3) * 2;
                const float b0 = sbo[c], b1 = sbo[c + 1];
                const float v0 = fmaxf(acc[mf][nf][0] + b0, 0.f);
                const float v1 = fmaxf(acc[mf][nf][1] + b1, 0.f);
                const float v2 = fmaxf(acc[mf][nf][2] + b0, 0.f);
                const float v3 = fmaxf(acc[mf][nf][3] + b1, 0.f);
                const unsigned off0 = sw_off(r,     c >> 3) + (c & 7) * 2;
                const unsigned off1 = sw_off(r + 8, c >> 3) + (c & 7) * 2;
                *(unsigned*)(sm + CSM_AHI + off0) = pack_bf2(v0, v1);
                *(unsigned*)(sm + CSM_AHI + off1) = pack_bf2(v2, v3);
                *(unsigned*)(sm + CSM_ALO + off0) =
                    pack_bf2(v0 - bfhi(pack_bf2(0.f, v0)), v1 - bfhi(pack_bf2(0.f, v1)));
                *(unsigned*)(sm + CSM_ALO + off1) =
                    pack_bf2(v2 - bfhi(pack_bf2(0.f, v2)), v3 - bfhi(pack_bf2(0.f, v3)));
            }
        }
    }
    stage_w(sm, CSM_W1H, CSM_W1L, 6, tid);   // sem_wv
    __syncthreads();

    // phase 2: K1 = relu(Agg@wk+bk) — score path, 1-term
    mma_loop<1>(sb, CSM_AHI, CSM_ALO, CSM_W2H, CSM_W2L, wm, wn, lane, acc);
    epi_f32(acc, (const float*)(sm + CSM_BIAS + 512), K1, rowBase, wm, wn, lane, BATCH);

    // phase 3: V1 = relu(Agg@wv+bv) — value path, 3-term
    mma_loop<3>(sb, CSM_AHI, CSM_ALO, CSM_W1H, CSM_W1L, wm, wn, lane, acc);
    epi_f32(acc, (const float*)(sm + CSM_BIAS + 1024), V1, rowBase, wm, wn, lane, BATCH);
}

// ===========================================================================
// Fused sem attention + final projection (3-term)
// ===========================================================================
#define SSM_AHI  0u
#define SSM_ALO  32768u
#define SSM_WHI  65536u
#define SSM_WLO  98304u
#define SSM_BIAS 131072u
#define SSMEM    131584

__global__ void __launch_bounds__(256)
sem_final(const float* __restrict__ Q2, const float* __restrict__ K0,
          const float* __restrict__ K1, const float* __restrict__ V0,
          const float* __restrict__ V1, const float* __restrict__ bo2,
          float* __restrict__ out)
{
    extern __shared__ char sm[];
    const unsigned sb = smem_u32(sm);
    const int tid  = threadIdx.x;
    const int wid  = tid >> 5;
    const int lane = tid & 31;
    const int wm   = wid & 3;
    const int wn   = wid >> 2;
    const int rowBase = blockIdx.x * 128;

    if (tid < 128) ((float*)(sm + SSM_BIAS))[tid] = bo2[tid];

    const float scale = 0.08838834764831845f;
    #pragma unroll
    for (int u = 0; u < 8; u++) {
        const int g  = u * 256 + tid;
        const int r  = g >> 4, kc = g & 15;
        const long base = (long)(rowBase + r) * DIM + kc * 8;

        const float4 qa = *(const float4*)(Q2 + base);
        const float4 qb = *(const float4*)(Q2 + base + 4);
        const float4 k0a = *(const float4*)(K0 + base);
        const float4 k0b = *(const float4*)(K0 + base + 4);
        const float4 k1a = *(const float4*)(K1 + base);
        const float4 k1b = *(const float4*)(K1 + base + 4);

        float s0 = qa.x*k0a.x + qa.y*k0a.y + qa.z*k0a.z + qa.w*k0a.w
                 + qb.x*k0b.x + qb.y*k0b.y + qb.z*k0b.z + qb.w*k0b.w;
        float s1 = qa.x*k1a.x + qa.y*k1a.y + qa.z*k1a.z + qa.w*k1a.w
                 + qb.x*k1b.x + qb.y*k1b.y + qb.z*k1b.z + qb.w*k1b.w;
        #pragma unroll
        for (int o = 8; o; o >>= 1) {
            s0 += __shfl_xor_sync(0xffffffffu, s0, o);
            s1 += __shfl_xor_sync(0xffffffffu, s1, o);
        }
        s0 *= scale; s1 *= scale;
        const float m  = fmaxf(s0, s1);
        const float e0 = __expf(s0 - m);
        const float e1 = __expf(s1 - m);
        const float inv = 1.0f / (e0 + e1);
        const float p0 = e0 * inv, p1 = e1 * inv;

        const float4 v0a = *(const float4*)(V0 + base);
        const float4 v0b = *(const float4*)(V0 + base + 4);
        const float4 v1a = *(const float4*)(V1 + base);
        const float4 v1b = *(const float4*)(V1 + base + 4);
        const float xs[8] = {
            p0*v0a.x + p1*v1a.x, p0*v0a.y + p1*v1a.y,
            p0*v0a.z + p1*v1a.z, p0*v0a.w + p1*v1a.w,
            p0*v0b.x + p1*v1b.x, p0*v0b.y + p1*v1b.y,
            p0*v0b.z + p1*v1b.z, p0*v0b.w + p1*v1b.w };
        uint4 H, L;
        split8(xs, H, L);
        const unsigned o = sw_off(r, kc);
        *(uint4*)(sm + SSM_AHI + o) = H;
        *(uint4*)(sm + SSM_ALO + o) = L;
    }
    stage_w(sm, SSM_WHI, SSM_WLO, 7, tid);   // sem_wo
    __syncthreads();

    float acc[2][8][4];
    mma_loop<3>(sb, SSM_AHI, SSM_ALO, SSM_WHI, SSM_WLO, wm, wn, lane, acc);
    epi_f32(acc, (const float*)(sm + SSM_BIAS), out, rowBase, wm, wn, lane, BATCH);
}

// ---------------------------------------------------------------------------
// GAT attention v2 (exact R8 revert): paired-item 16B loads
// ---------------------------------------------------------------------------
__global__ void __launch_bounds__(256)
gat_attn(const float* __restrict__ Q, const int* __restrict__ movies,
         const __nv_bfloat16* __restrict__ KV, float* __restrict__ Y)
{
    const int w    = threadIdx.x >> 5;
    const int lane = threadIdx.x & 31;
    const int half = lane >> 4;
    const int cl   = lane & 15;
    const int b    = blockIdx.x * 8 + w;

    __shared__ int   sidx[8][NHIST];
    __shared__ float sp  [8][NHIST];

    if (lane < NHIST)      sidx[w][lane]      = movies[(b * NHIST + lane) * 2];
    if (lane + 32 < NHIST) sidx[w][lane + 32] = movies[(b * NHIST + lane + 32) * 2];
    __syncwarp();

    const float4 qa = *(const float4*)(Q + (long)b * DIM + cl * 8);
    const float4 qb = *(const float4*)(Q + (long)b * DIM + cl * 8 + 4);

    #pragma unroll
    for (int t0 = 0; t0 < 25; t0 += 5) {
        uint4 kr[5];
        #pragma unroll
        for (int j = 0; j < 5; j++)
            kr[j] = *(const uint4*)(KV + (long)sidx[w][2*(t0+j) + half] * 256 + cl * 8);
        float sc[5];
        #pragma unroll
        for (int j = 0; j < 5; j++) {
            float s;
            s  = qa.x * bflo(kr[j].x) + qa.y * bfhi(kr[j].x);
            s += qa.z * bflo(kr[j].y) + qa.w * bfhi(kr[j].y);
            s += qb.x * bflo(kr[j].z) + qb.y * bfhi(kr[j].z);
            s += qb.z * bflo(kr[j].w) + qb.w * bfhi(kr[j].w);
            sc[j] = s;
        }
        #pragma unroll
        for (int j = 0; j < 5; j++)
            #pragma unroll
            for (int off = 8; off; off >>= 1)
                sc[j] += __shfl_xor_sync(0xffffffffu, sc[j], off);
        if (cl == 0) {
            #pragma unroll
            for (int j = 0; j < 5; j++) sp[w][2*(t0+j) + half] = sc[j];
        }
    }
    __syncwarp();

    const float scale = 0.08838834764831845f;
    float a0 = (lane < NHIST)      ? sp[w][lane]      * scale : -1e30f;
    float a1 = (lane + 32 < NHIST) ? sp[w][lane + 32] * scale : -1e30f;
    float m = fmaxf(a0, a1);
    #pragma unroll
    for (int off = 16; off; off >>= 1)
        m = fmaxf(m, __shfl_xor_sync(0xffffffffu, m, off));
    float e0 = (lane < NHIST)      ? __expf(a0 - m) : 0.f;
    float e1 = (lane + 32 < NHIST) ? __expf(a1 - m) : 0.f;
    float es = e0 + e1;
    #pragma unroll
    for (int off = 16; off; off >>= 1)
        es += __shfl_xor_sync(0xffffffffu, es, off);
    const float inv = 1.0f / es;
    if (lane < NHIST)      sp[w][lane]      = e0 * inv;
    if (lane + 32 < NHIST) sp[w][lane + 32] = e1 * inv;
    __syncwarp();

    float acc[8];
    #pragma unroll
    for (int i = 0; i < 8; i++) acc[i] = 0.f;

    #pragma unroll
    for (int t0 = 0; t0 < 25; t0 += 5) {
        uint4 vr[5];
        float pj[5];
        #pragma unroll
        for (int j = 0; j < 5; j++) {
            vr[j] = *(const uint4*)(KV + (long)sidx[w][2*(t0+j) + half] * 256 + 128 + cl * 8);
            pj[j] = sp[w][2*(t0+j) + half];
        }
        #pragma unroll
        for (int j = 0; j < 5; j++) {
            acc[0] = fmaf(pj[j], bflo(vr[j].x), acc[0]);
            acc[1] = fmaf(pj[j], bfhi(vr[j].x), acc[1]);
            acc[2] = fmaf(pj[j], bflo(vr[j].y), acc[2]);
            acc[3] = fmaf(pj[j], bfhi(vr[j].y), acc[3]);
            acc[4] = fmaf(pj[j], bflo(vr[j].z), acc[4]);
            acc[5] = fmaf(pj[j], bfhi(vr[j].z), acc[5]);
            acc[6] = fmaf(pj[j], bflo(vr[j].w), acc[6]);
            acc[7] = fmaf(pj[j], bfhi(vr[j].w), acc[7]);
        }
    }
    #pragma unroll
    for (int i = 0; i < 8; i++)
        acc[i] += __shfl_xor_sync(0xffffffffu, acc[i], 16);

    if (half == 0) {
        *(float4*)(Y + (long)b * DIM + cl * 8)     = make_float4(acc[0], acc[1], acc[2], acc[3]);
        *(float4*)(Y + (long)b * DIM + cl * 8 + 4) = make_float4(acc[4], acc[5], acc[6], acc[7]);
    }
}

// ---------------------------------------------------------------------------
// Host launcher (6 launches)
// ---------------------------------------------------------------------------
extern "C" void kernel_launch(void* const* d_in, const int* in_sizes, int n_in,
                              void* d_out, int out_size)
{
    const int*   uids       = (const int*)  d_in[0];
    const int*   u_movies   = (const int*)  d_in[2];
    const float* user_table = (const float*)d_in[3];
    const float* item_table = (const float*)d_in[5];
    const float* gat_wq = (const float*)d_in[6],  *gat_bq = (const float*)d_in[7];
    const float* gat_wk = (const float*)d_in[8],  *gat_bk = (const float*)d_in[9];
    const float* gat_wv = (const float*)d_in[10], *gat_bv = (const float*)d_in[11];
    const float* gat_wo = (const float*)d_in[12], *gat_bo = (const float*)d_in[13];
    const float* sem_wq = (const float*)d_in[14], *sem_bq = (const float*)d_in[15];
    const float* sem_wk = (const float*)d_in[16], *sem_bk = (const float*)d_in[17];
    const float* sem_wv = (const float*)d_in[18], *sem_bv = (const float*)d_in[19];
    const float* sem_wo = (const float*)d_in[20], *sem_bo = (const float*)d_in[21];
    float* out = (float*)d_out;

    __nv_bfloat16* KV;
    unsigned short *Wh0, *Wh1;
    float *Qg, *Q2, *K0, *V0, *K1, *V1, *Y;
    cudaGetSymbolAddress((void**)&KV,  g_KV);
    cudaGetSymbolAddress((void**)&Qg,  g_Qg);
    cudaGetSymbolAddress((void**)&Q2,  g_Q2);
    cudaGetSymbolAddress((void**)&K0,  g_K0);
    cudaGetSymbolAddress((void**)&V0,  g_V0);
    cudaGetSymbolAddress((void**)&K1,  g_K1);
    cudaGetSymbolAddress((void**)&V1,  g_V1);
    cudaGetSymbolAddress((void**)&Y,   g_Y);
    {
        void* p;
        cudaGetSymbolAddress(&p, g_Wh);
        Wh0 = (unsigned short*)p;
        Wh1 = Wh0 + DIM * DIM;
    }

    static bool attr_done = false;
    if (!attr_done) {
        cudaFuncSetAttribute(node_all,  cudaFuncAttributeMaxDynamicSharedMemorySize, NSMEM);
        cudaFuncSetAttribute(gemm_item, cudaFuncAttributeMaxDynamicSharedMemorySize, ISMEM);
        cudaFuncSetAttribute(agg_chain, cudaFuncAttributeMaxDynamicSharedMemorySize, CSMEM);
        cudaFuncSetAttribute(sem_final, cudaFuncAttributeMaxDynamicSharedMemorySize, SSMEM);
        attr_done = true;
    }

    const dim3 blk(256);
    const int gItems = (NITEMS + 127) / 128;     // 782
    const int gBatch = BATCH / 128;              // 128

    // 0: weight transpose + splits
    w_setup<<<64, 256>>>(gat_wq, gat_wk, gat_wv, gat_wo,
                         sem_wq, sem_wk, sem_wv, sem_wo);

    // 1: item K/V -> bf16 KV table (single-term fp16)
    gemm_item<<<dim3(gItems, 2), blk, ISMEM>>>(item_table, Wh0, Wh1,
                                               gat_bk, gat_bv, KV, NITEMS);

    // 2: fused node transforms (A gathered+split once; 4 phases)
    node_all<<<gBatch, blk, NSMEM>>>(user_table, uids,
                                     gat_bq, sem_bq, sem_bk, sem_bv,
                                     Qg, Q2, K0, V0);

    // 3: GAT attention (R8 version)
    gat_attn<<<BATCH / 8, blk>>>(Qg, u_movies, KV, Y);

    // 4: fused Agg -> K1 (1-term), V1 (3-term)
    agg_chain<<<gBatch, blk, CSMEM>>>(Y, gat_bo, sem_bk, sem_bv, K1, V1);

    // 5: fused sem attention + final projection into d_out
    sem_final<<<gBatch, blk, SSMEM>>>(Q2, K0, K1, V0, V1, sem_bo, out);
}

// round 11
// speedup vs baseline: 1.1452x; 1.0177x over previous
#include <cuda_runtime.h>
#include <cuda_bf16.h>
#include <cuda_fp16.h>
#include <math.h>

// ---------------------------------------------------------------------------
// Problem constants
// ---------------------------------------------------------------------------
#define BATCH   16384
#define NHIST   50
#define DIM     128
#define NITEMS  100000

// ---------------------------------------------------------------------------
// Scratch (static device globals)
// ---------------------------------------------------------------------------
__device__ __nv_bfloat16 g_KV[NITEMS * 256];   // per item: 128 bf16 K | 128 bf16 V
__device__ float g_Qg [BATCH * DIM];
__device__ float g_Q2 [BATCH * DIM];
__device__ float g_K0 [BATCH * DIM];
__device__ float g_V0 [BATCH * DIM];
__device__ float g_K1 [BATCH * DIM];
__device__ float g_V1 [BATCH * DIM];
__device__ float g_Y  [BATCH * DIM];
// bf16 weight splits, transposed to [n][k]: slot 2*w = hi, 2*w+1 = lo
// w: 0=gat_wq 1=gat_wk 2=gat_wv 3=gat_wo 4=sem_wq 5=sem_wk 6=sem_wv 7=sem_wo
__device__ unsigned short g_W4[16][DIM * DIM];
// fp16 transposed weights for the item GEMM: 0=gat_wk, 1=gat_wv
__device__ unsigned short g_Wh[2][DIM * DIM];

// ---------------------------------------------------------------------------
// helpers
// ---------------------------------------------------------------------------
__device__ __forceinline__ unsigned smem_u32(const void* p) {
    unsigned a;
    asm("{ .reg .u64 t; cvta.to.shared.u64 t, %1; cvt.u32.u64 %0, t; }"
        : "=r"(a) : "l"(p));
    return a;
}
__device__ __forceinline__ void ldm4(unsigned& r0, unsigned& r1,
                                     unsigned& r2, unsigned& r3, unsigned addr) {
    asm volatile("ldmatrix.sync.aligned.m8n8.x4.shared.b16 {%0,%1,%2,%3}, [%4];"
                 : "=r"(r0), "=r"(r1), "=r"(r2), "=r"(r3) : "r"(addr));
}
__device__ __forceinline__ void mma_bf16(float* d, const unsigned* a, const unsigned* b) {
    asm volatile("mma.sync.aligned.m16n8k16.row.col.f32.bf16.bf16.f32 "
                 "{%0,%1,%2,%3}, {%4,%5,%6,%7}, {%8,%9}, {%0,%1,%2,%3};"
                 : "+f"(d[0]), "+f"(d[1]), "+f"(d[2]), "+f"(d[3])
                 : "r"(a[0]), "r"(a[1]), "r"(a[2]), "r"(a[3]),
                   "r"(b[0]), "r"(b[1]));
}
__device__ __forceinline__ void mma_f16(float* d, const unsigned* a, const unsigned* b) {
    asm volatile("mma.sync.aligned.m16n8k16.row.col.f32.f16.f16.f32 "
                 "{%0,%1,%2,%3}, {%4,%5,%6,%7}, {%8,%9}, {%0,%1,%2,%3};"
                 : "+f"(d[0]), "+f"(d[1]), "+f"(d[2]), "+f"(d[3])
                 : "r"(a[0]), "r"(a[1]), "r"(a[2]), "r"(a[3]),
                   "r"(b[0]), "r"(b[1]));
}
// smem byte offset for (row, 8-elem 16B chunk kc): 256B rows, XOR swizzle
__device__ __forceinline__ unsigned sw_off(int row, int kc) {
    return (unsigned)(row * 256 + ((kc ^ (row & 7)) << 4));
}
// split 8 fp32 -> two uint4 of bf16 (hi, lo = residual)
__device__ __forceinline__ void split8(const float* xs, uint4& H, uint4& L) {
    unsigned hw[4], lw[4];
    #pragma unroll
    for (int j = 0; j < 4; j++) {
        __nv_bfloat16 h0 = __float2bfloat16(xs[2*j]);
        __nv_bfloat16 h1 = __float2bfloat16(xs[2*j+1]);
        __nv_bfloat16 l0 = __float2bfloat16(xs[2*j]   - __bfloat162float(h0));
        __nv_bfloat16 l1 = __float2bfloat16(xs[2*j+1] - __bfloat162float(h1));
        hw[j] = (unsigned)*(unsigned short*)&h0 | ((unsigned)*(unsigned short*)&h1 << 16);
        lw[j] = (unsigned)*(unsigned short*)&l0 | ((unsigned)*(unsigned short*)&l1 << 16);
    }
    H = make_uint4(hw[0], hw[1], hw[2], hw[3]);
    L = make_uint4(lw[0], lw[1], lw[2], lw[3]);
}
// 8 fp32 -> uint4 of fp16
__device__ __forceinline__ uint4 pack8f16(const float* xs) {
    unsigned hw[4];
    #pragma unroll
    for (int j = 0; j < 4; j++) {
        const unsigned short a = __half_as_ushort(__float2half_rn(xs[2*j]));
        const unsigned short b = __half_as_ushort(__float2half_rn(xs[2*j+1]));
        hw[j] = (unsigned)a | ((unsigned)b << 16);
    }
    return make_uint4(hw[0], hw[1], hw[2], hw[3]);
}
__device__ __forceinline__ unsigned pack_bf2(float a, float b) {
    __nv_bfloat16 x = __float2bfloat16(a), y = __float2bfloat16(b);
    return (unsigned)*(unsigned short*)&x | ((unsigned)*(unsigned short*)&y << 16);
}
// bf16x2 unpack via shift/mask
__device__ __forceinline__ float bflo(unsigned u) { return __uint_as_float(u << 16); }
__device__ __forceinline__ float bfhi(unsigned u) { return __uint_as_float(u & 0xffff0000u); }

// ===========================================================================
// Setup: transpose + split all weight matrices
// ===========================================================================
__global__ void w_setup(const float* w0, const float* w1, const float* w2,
                        const float* w3, const float* w4, const float* w5,
                        const float* w6, const float* w7)
{
    const int i = blockIdx.x * blockDim.x + threadIdx.x;
    if (i >= DIM * DIM) return;
    const float* ws[8] = {w0, w1, w2, w3, w4, w5, w6, w7};
    const int k = i >> 7, n = i & 127;
    const int dst = n * DIM + k;
    #pragma unroll
    for (int w = 0; w < 8; w++) {
        const float a = ws[w][i];
        __nv_bfloat16 h = __float2bfloat16(a);
        __nv_bfloat16 l = __float2bfloat16(a - __bfloat162float(h));
        g_W4[2*w    ][dst] = *(unsigned short*)&h;
        g_W4[2*w + 1][dst] = *(unsigned short*)&l;
    }
    g_Wh[0][dst] = __half_as_ushort(__float2half_rn(w1[i]));   // gat_wk
    g_Wh[1][dst] = __half_as_ushort(__float2half_rn(w2[i]));   // gat_wv
}

// ===========================================================================
// Shared GEMM building blocks. 8 warps (4x2), warp tile 32x64, CTA 128x128.
// ===========================================================================
template<int TERMS>
__device__ __forceinline__ void mma_loop(
    unsigned sb, unsigned oAhi, unsigned oAlo, unsigned oWhi, unsigned oWlo,
    int wm, int wn, int lane, float acc[2][8][4])
{
    #pragma unroll
    for (int i = 0; i < 2; i++)
        #pragma unroll
        for (int j = 0; j < 8; j++)
            #pragma unroll
            for (int q = 0; q < 4; q++) acc[i][j][q] = 0.f;

    #pragma unroll
    for (int ks = 0; ks < 8; ks++) {
        unsigned aH[2][4], aL[2][4], bH[8][2], bL[8][2];
        {
            const int r  = wm * 32 + (lane & 15);
            const int kc = ks * 2 + (lane >> 4);
            ldm4(aH[0][0], aH[0][1], aH[0][2], aH[0][3], sb + oAhi + sw_off(r,      kc));
            ldm4(aH[1][0], aH[1][1], aH[1][2], aH[1][3], sb + oAhi + sw_off(r + 16, kc));
            if (TERMS == 3) {
                ldm4(aL[0][0], aL[0][1], aL[0][2], aL[0][3], sb + oAlo + sw_off(r,      kc));
                ldm4(aL[1][0], aL[1][1], aL[1][2], aL[1][3], sb + oAlo + sw_off(r + 16, kc));
            }
        }
        {
            const int grp  = lane >> 3;
            const int nloc = (lane & 7) + ((grp >> 1) << 3);
            const int kc   = ks * 2 + (grp & 1);
            #pragma unroll
            for (int j = 0; j < 4; j++) {
                const int n = wn * 64 + j * 16 + nloc;
                ldm4(bH[2*j][0], bH[2*j][1], bH[2*j+1][0], bH[2*j+1][1],
                     sb + oWhi + sw_off(n, kc));
                if (TERMS == 3)
                    ldm4(bL[2*j][0], bL[2*j][1], bL[2*j+1][0], bL[2*j+1][1],
                         sb + oWlo + sw_off(n, kc));
            }
        }
        #pragma unroll
        for (int mf = 0; mf < 2; mf++)
            #pragma unroll
            for (int nf = 0; nf < 8; nf++) {
                mma_bf16(acc[mf][nf], aH[mf], bH[nf]);
                if (TERMS == 3) {
                    mma_bf16(acc[mf][nf], aH[mf], bL[nf]);
                    mma_bf16(acc[mf][nf], aL[mf], bH[nf]);
                }
            }
    }
}

__device__ __forceinline__ void epi_f32(
    float acc[2][8][4], const float* sbias, float* C,
    int rowBase, int wm, int wn, int lane, int M)
{
    #pragma unroll
    for (int mf = 0; mf < 2; mf++) {
        const int r0 = rowBase + wm * 32 + mf * 16 + (lane >> 2);
        #pragma unroll
        for (int nf = 0; nf < 8; nf++) {
            const int c  = wn * 64 + nf * 8 + (lane & 3) * 2;
            const float b0 = sbias[c], b1 = sbias[c + 1];
            if (r0 < M)
                *(float2*)(C + (long)r0 * DIM + c) =
                    make_float2(fmaxf(acc[mf][nf][0] + b0, 0.f),
                                fmaxf(acc[mf][nf][1] + b1, 0.f));
            if (r0 + 8 < M)
                *(float2*)(C + (long)(r0 + 8) * DIM + c) =
                    make_float2(fmaxf(acc[mf][nf][2] + b0, 0.f),
                                fmaxf(acc[mf][nf][3] + b1, 0.f));
        }
    }
}

__device__ __forceinline__ void stage_w(
    char* sm, unsigned oWhi, unsigned oWlo, int wslot, int tid)
{
    const unsigned short* WH = g_W4[2 * wslot];
    const unsigned short* WL = g_W4[2 * wslot + 1];
    #pragma unroll
    for (int u = 0; u < 8; u++) {
        const int g  = u * 256 + tid;
        const int n  = g >> 4, kc = g & 15;
        const unsigned o = sw_off(n, kc);
        *(uint4*)(sm + oWhi + o) = *(const uint4*)(WH + n * DIM + kc * 8);
        *(uint4*)(sm + oWlo + o) = *(const uint4*)(WL + n * DIM + kc * 8);
    }
}

// ===========================================================================
// Fused node transforms (unchanged from R10)
// ===========================================================================
#define NSM_AHI  0u
#define NSM_ALO  32768u
#define NSM_WHI  65536u
#define NSM_WLO  98304u
#define NSM_BIAS 131072u
#define NSMEM    133120

__global__ void __launch_bounds__(256)
node_all(const float* __restrict__ A, const int* __restrict__ gidx,
         const float* __restrict__ bq, const float* __restrict__ bq2,
         const float* __restrict__ bk, const float* __restrict__ bv,
         float* __restrict__ Qg, float* __restrict__ Q2,
         float* __restrict__ K0, float* __restrict__ V0)
{
    extern __shared__ char sm[];
    const unsigned sb = smem_u32(sm);
    const int tid  = threadIdx.x;
    const int wid  = tid >> 5;
    const int lane = tid & 31;
    const int wm   = wid & 3;
    const int wn   = wid >> 2;
    const int rowBase = blockIdx.x * 128;

    if (tid < 128) {
        ((float*)(sm + NSM_BIAS))[tid]        = bq[tid];
        ((float*)(sm + NSM_BIAS + 512))[tid]  = bq2[tid];
        ((float*)(sm + NSM_BIAS + 1024))[tid] = bk[tid];
        ((float*)(sm + NSM_BIAS + 1536))[tid] = bv[tid];
    }

    #pragma unroll
    for (int u = 0; u < 8; u++) {
        const int g  = u * 256 + tid;
        const int r  = g >> 4, kc = g & 15;
        const int src = gidx[rowBase + r];
        const float4 x0 = *(const float4*)(A + (long)src * DIM + kc * 8);
        const float4 x1 = *(const float4*)(A + (long)src * DIM + kc * 8 + 4);
        const float xs[8] = {x0.x, x0.y, x0.z, x0.w, x1.x, x1.y, x1.z, x1.w};
        uint4 H, L;
        split8(xs, H, L);
        const unsigned o = sw_off(r, kc);
        *(uint4*)(sm + NSM_AHI + o) = H;
        *(uint4*)(sm + NSM_ALO + o) = L;
    }
    stage_w(sm, NSM_WHI, NSM_WLO, 0, tid);   // gat_wq
    __syncthreads();

    float acc[2][8][4];

    mma_loop<1>(sb, NSM_AHI, NSM_ALO, NSM_WHI, NSM_WLO, wm, wn, lane, acc);
    __syncthreads();
    stage_w(sm, NSM_WHI, NSM_WLO, 4, tid);   // sem_wq
    epi_f32(acc, (const float*)(sm + NSM_BIAS), Qg, rowBase, wm, wn, lane, BATCH);
    __syncthreads();

    mma_loop<1>(sb, NSM_AHI, NSM_ALO, NSM_WHI, NSM_WLO, wm, wn, lane, acc);
    __syncthreads();
    stage_w(sm, NSM_WHI, NSM_WLO, 5, tid);   // sem_wk
    epi_f32(acc, (const float*)(sm + NSM_BIAS + 512), Q2, rowBase, wm, wn, lane, BATCH);
    __syncthreads();

    mma_loop<1>(sb, NSM_AHI, NSM_ALO, NSM_WHI, NSM_WLO, wm, wn, lane, acc);
    __syncthreads();
    stage_w(sm, NSM_WHI, NSM_WLO, 6, tid);   // sem_wv
    epi_f32(acc, (const float*)(sm + NSM_BIAS + 1024), K0, rowBase, wm, wn, lane, BATCH);
    __syncthreads();

    mma_loop<3>(sb, NSM_AHI, NSM_ALO, NSM_WHI, NSM_WLO, wm, wn, lane, acc);
    epi_f32(acc, (const float*)(sm + NSM_BIAS + 1536), V0, rowBase, wm, wn, lane, BATCH);
}

// ===========================================================================
// Item GEMM: single-term fp16 (output re-rounded to bf16 KV table)
// ===========================================================================
#define ISM_A    0u
#define ISM_W    32768u
#define ISM_BIAS 65536u
#define ISMEM    66048

__global__ void __launch_bounds__(256)
gemm_item(const float* __restrict__ A,
          const unsigned short* __restrict__ W0, const unsigned short* __restrict__ W1,
          const float* __restrict__ b0, const float* __restrict__ b1,
          __nv_bfloat16* __restrict__ KV, int M)
{
    const int y = blockIdx.y;
    const unsigned short* Wt = y ? W1 : W0;
    const float* bias = y ? b1 : b0;
    __nv_bfloat16* Cb = KV + (y ? 128 : 0);

    extern __shared__ char sm[];
    const unsigned sb = smem_u32(sm);
    const int tid  = threadIdx.x;
    const int wid  = tid >> 5;
    const int lane = tid & 31;
    const int wm   = wid & 3;
    const int wn   = wid >> 2;
    const int rowBase = blockIdx.x * 128;

    if (tid < 128) ((float*)(sm + ISM_BIAS))[tid] = bias[tid];

    #pragma unroll
    for (int u = 0; u < 8; u++) {
        const int g  = u * 256 + tid;
        const int r  = g >> 4, kc = g & 15;
        int R = rowBase + r; if (R >= M) R = M - 1;
        const float4 x0 = *(const float4*)(A + (long)R * DIM + kc * 8);
        const float4 x1 = *(const float4*)(A + (long)R * DIM + kc * 8 + 4);
        const float xs[8] = {x0.x, x0.y, x0.z, x0.w, x1.x, x1.y, x1.z, x1.w};
        *(uint4*)(sm + ISM_A + sw_off(r, kc)) = pack8f16(xs);
    }
    #pragma unroll
    for (int u = 0; u < 8; u++) {
        const int g  = u * 256 + tid;
        const int n  = g >> 4, kc = g & 15;
        *(uint4*)(sm + ISM_W + sw_off(n, kc)) = *(const uint4*)(Wt + n * DIM + kc * 8);
    }
    __syncthreads();

    float acc[2][8][4];
    #pragma unroll
    for (int i = 0; i < 2; i++)
        #pragma unroll
        for (int j = 0; j < 8; j++)
            #pragma unroll
            for (int q = 0; q < 4; q++) acc[i][j][q] = 0.f;

    #pragma unroll
    for (int ks = 0; ks < 8; ks++) {
        unsigned aH[2][4], bH[8][2];
        {
            const int r  = wm * 32 + (lane & 15);
            const int kc = ks * 2 + (lane >> 4);
            ldm4(aH[0][0], aH[0][1], aH[0][2], aH[0][3], sb + ISM_A + sw_off(r,      kc));
            ldm4(aH[1][0], aH[1][1], aH[1][2], aH[1][3], sb + ISM_A + sw_off(r + 16, kc));
        }
        {
            const int grp  = lane >> 3;
            const int nloc = (lane & 7) + ((grp >> 1) << 3);
            const int kc   = ks * 2 + (grp & 1);
            #pragma unroll
            for (int j = 0; j < 4; j++) {
                const int n = wn * 64 + j * 16 + nloc;
                ldm4(bH[2*j][0], bH[2*j][1], bH[2*j+1][0], bH[2*j+1][1],
                     sb + ISM_W + sw_off(n, kc));
            }
        }
        #pragma unroll
        for (int mf = 0; mf < 2; mf++)
            #pragma unroll
            for (int nf = 0; nf < 8; nf++)
                mma_f16(acc[mf][nf], aH[mf], bH[nf]);
    }

    const float* sbias = (const float*)(sm + ISM_BIAS);
    #pragma unroll
    for (int mf = 0; mf < 2; mf++) {
        const int r0 = rowBase + wm * 32 + mf * 16 + (lane >> 2);
        #pragma unroll
        for (int nf = 0; nf < 8; nf++) {
            const int c  = wn * 64 + nf * 8 + (lane & 3) * 2;
            const float b0v = sbias[c], b1v = sbias[c + 1];
            if (r0 < M) {
                const unsigned v = pack_bf2(fmaxf(acc[mf][nf][0] + b0v, 0.f),
                                            fmaxf(acc[mf][nf][1] + b1v, 0.f));
                *(unsigned*)(Cb + (long)r0 * 256 + c) = v;
            }
            if (r0 + 8 < M) {
                const unsigned v = pack_bf2(fmaxf(acc[mf][nf][2] + b0v, 0.f),
                                            fmaxf(acc[mf][nf][3] + b1v, 0.f));
                *(unsigned*)(Cb + (long)(r0 + 8) * 256 + c) = v;
            }
        }
    }
}

// ===========================================================================
// Fused chain: Agg -> K1 (1-term), V1 (3-term)   (unchanged from R10)
// ===========================================================================
#define CSM_AHI  0u
#define CSM_ALO  32768u
#define CSM_W1H  65536u
#define CSM_W1L  98304u
#define CSM_W2H  131072u
#define CSM_W2L  163840u
#define CSM_BIAS 196608u
#define CSMEM    198144

__global__ void __launch_bounds__(256)
agg_chain(const float* __restrict__ Y,
          const float* __restrict__ bo, const float* __restrict__ bk,
          const float* __restrict__ bv,
          float* __restrict__ K1, float* __restrict__ V1)
{
    extern __shared__ char sm[];
    const unsigned sb = smem_u32(sm);
    const int tid  = threadIdx.x;
    const int wid  = tid >> 5;
    const int lane = tid & 31;
    const int wm   = wid & 3;
    const int wn   = wid >> 2;
    const int rowBase = blockIdx.x * 128;

    if (tid < 128) {
        ((float*)(sm + CSM_BIAS))[tid]       = bo[tid];
        ((float*)(sm + CSM_BIAS + 512))[tid] = bk[tid];
        ((float*)(sm + CSM_BIAS + 1024))[tid]= bv[tid];
    }

    #pragma unroll
    for (int u = 0; u < 8; u++) {
        const int g  = u * 256 + tid;
        const int r  = g >> 4, kc = g & 15;
        const int R = rowBase + r;
        const float4 x0 = *(const float4*)(Y + (long)R * DIM + kc * 8);
        const float4 x1 = *(const float4*)(Y + (long)R * DIM + kc * 8 + 4);
        const float xs[8] = {x0.x, x0.y, x0.z, x0.w, x1.x, x1.y, x1.z, x1.w};
        uint4 H, L;
        split8(xs, H, L);
        const unsigned o = sw_off(r, kc);
        *(uint4*)(sm + CSM_AHI + o) = H;
        *(uint4*)(sm + CSM_ALO + o) = L;
    }
    stage_w(sm, CSM_W1H, CSM_W1L, 3, tid);   // gat_wo
    stage_w(sm, CSM_W2H, CSM_W2L, 5, tid);   // sem_wk
    __syncthreads();

    float acc[2][8][4];

    mma_loop<3>(sb, CSM_AHI, CSM_ALO, CSM_W1H, CSM_W1L, wm, wn, lane, acc);
    __syncthreads();

    {
        const float* sbo = (const float*)(sm + CSM_BIAS);
        #pragma unroll
        for (int mf = 0; mf < 2; mf++) {
            const int r = wm * 32 + mf * 16 + (lane >> 2);
            #pragma unroll
            for (int nf = 0; nf < 8; nf++) {
                const int c  = wn * 64 + nf * 8 + (lane & 3) * 2;
                const float b0 = sbo[c], b1 = sbo[c + 1];
                const float v0 = fmaxf(acc[mf][nf][0] + b0, 0.f);
                const float v1 = fmaxf(acc[mf][nf][1] + b1, 0.f);
                const float v2 = fmaxf(acc[mf][nf][2] + b0, 0.f);
                const float v3 = fmaxf(acc[mf][nf][3] + b1, 0.f);
                const unsigned off0 = sw_off(r,     c >> 3) + (c & 7) * 2;
                const unsigned off1 = sw_off(r + 8, c >> 3) + (c & 7) * 2;
                *(unsigned*)(sm + CSM_AHI + off0) = pack_bf2(v0, v1);
                *(unsigned*)(sm + CSM_AHI + off1) = pack_bf2(v2, v3);
                *(unsigned*)(sm + CSM_ALO + off0) =
                    pack_bf2(v0 - bfhi(pack_bf2(0.f, v0)), v1 - bfhi(pack_bf2(0.f, v1)));
                *(unsigned*)(sm + CSM_ALO + off1) =
                    pack_bf2(v2 - bfhi(pack_bf2(0.f, v2)), v3 - bfhi(pack_bf2(0.f, v3)));
            }
        }
    }
    stage_w(sm, CSM_W1H, CSM_W1L, 6, tid);   // sem_wv
    __syncthreads();

    mma_loop<1>(sb, CSM_AHI, CSM_ALO, CSM_W2H, CSM_W2L, wm, wn, lane, acc);
    epi_f32(acc, (const float*)(sm + CSM_BIAS + 512), K1, rowBase, wm, wn, lane, BATCH);

    mma_loop<3>(sb, CSM_AHI, CSM_ALO, CSM_W1H, CSM_W1L, wm, wn, lane, acc);
    epi_f32(acc, (const float*)(sm + CSM_BIAS + 1024), V1, rowBase, wm, wn, lane, BATCH);
}

// ===========================================================================
// Fused sem attention + final projection (unchanged from R10)
// ===========================================================================
#define SSM_AHI  0u
#define SSM_ALO  32768u
#define SSM_WHI  65536u
#define SSM_WLO  98304u
#define SSM_BIAS 131072u
#define SSMEM    131584

__global__ void __launch_bounds__(256)
sem_final(const float* __restrict__ Q2, const float* __restrict__ K0,
          const float* __restrict__ K1, const float* __restrict__ V0,
          const float* __restrict__ V1, const float* __restrict__ bo2,
          float* __restrict__ out)
{
    extern __shared__ char sm[];
    const unsigned sb = smem_u32(sm);
    const int tid  = threadIdx.x;
    const int wid  = tid >> 5;
    const int lane = tid & 31;
    const int wm   = wid & 3;
    const int wn   = wid >> 2;
    const int rowBase = blockIdx.x * 128;

    if (tid < 128) ((float*)(sm + SSM_BIAS))[tid] = bo2[tid];

    const float scale = 0.08838834764831845f;
    #pragma unroll
    for (int u = 0; u < 8; u++) {
        const int g  = u * 256 + tid;
        const int r  = g >> 4, kc = g & 15;
        const long base = (long)(rowBase + r) * DIM + kc * 8;

        const float4 qa = *(const float4*)(Q2 + base);
        const float4 qb = *(const float4*)(Q2 + base + 4);
        const float4 k0a = *(const float4*)(K0 + base);
        const float4 k0b = *(const float4*)(K0 + base + 4);
        const float4 k1a = *(const float4*)(K1 + base);
        const float4 k1b = *(const float4*)(K1 + base + 4);

        float s0 = qa.x*k0a.x + qa.y*k0a.y + qa.z*k0a.z + qa.w*k0a.w
                 + qb.x*k0b.x + qb.y*k0b.y + qb.z*k0b.z + qb.w*k0b.w;
        float s1 = qa.x*k1a.x + qa.y*k1a.y + qa.z*k1a.z + qa.w*k1a.w
                 + qb.x*k1b.x + qb.y*k1b.y + qb.z*k1b.z + qb.w*k1b.w;
        #pragma unroll
        for (int o = 8; o; o >>= 1) {
            s0 += __shfl_xor_sync(0xffffffffu, s0, o);
            s1 += __shfl_xor_sync(0xffffffffu, s1, o);
        }
        s0 *= scale; s1 *= scale;
        const float m  = fmaxf(s0, s1);
        const float e0 = __expf(s0 - m);
        const float e1 = __expf(s1 - m);
        const float inv = 1.0f / (e0 + e1);
        const float p0 = e0 * inv, p1 = e1 * inv;

        const float4 v0a = *(const float4*)(V0 + base);
        const float4 v0b = *(const float4*)(V0 + base + 4);
        const float4 v1a = *(const float4*)(V1 + base);
        const float4 v1b = *(const float4*)(V1 + base + 4);
        const float xs[8] = {
            p0*v0a.x + p1*v1a.x, p0*v0a.y + p1*v1a.y,
            p0*v0a.z + p1*v1a.z, p0*v0a.w + p1*v1a.w,
            p0*v0b.x + p1*v1b.x, p0*v0b.y + p1*v1b.y,
            p0*v0b.z + p1*v1b.z, p0*v0b.w + p1*v1b.w };
        uint4 H, L;
        split8(xs, H, L);
        const unsigned o = sw_off(r, kc);
        *(uint4*)(sm + SSM_AHI + o) = H;
        *(uint4*)(sm + SSM_ALO + o) = L;
    }
    stage_w(sm, SSM_WHI, SSM_WLO, 7, tid);   // sem_wo
    __syncthreads();

    float acc[2][8][4];
    mma_loop<3>(sb, SSM_AHI, SSM_ALO, SSM_WHI, SSM_WLO, wm, wn, lane, acc);
    epi_f32(acc, (const float*)(sm + SSM_BIAS), out, rowBase, wm, wn, lane, BATCH);
}

// ---------------------------------------------------------------------------
// GAT attention v4: ONE-PASS online softmax (no max-sub — validated R9).
// Half-warp h handles item 2t+h; lane covers cols (lane&15)*8..+7.
// num/den accumulated in-loop; single normalize at the end.
// ---------------------------------------------------------------------------
__global__ void __launch_bounds__(256)
gat_attn(const float* __restrict__ Q, const int* __restrict__ movies,
         const __nv_bfloat16* __restrict__ KV, float* __restrict__ Y)
{
    const int w    = threadIdx.x >> 5;
    const int lane = threadIdx.x & 31;
    const int half = lane >> 4;
    const int cl   = lane & 15;
    const int b    = blockIdx.x * 8 + w;

    __shared__ int sidx[8][NHIST];

    if (lane < NHIST)      sidx[w][lane]      = movies[(b * NHIST + lane) * 2];
    if (lane + 32 < NHIST) sidx[w][lane + 32] = movies[(b * NHIST + lane + 32) * 2];
    __syncwarp();

    // q chunk, pre-scaled by 1/sqrt(D)
    const float scale = 0.08838834764831845f;
    float4 qa = *(const float4*)(Q + (long)b * DIM + cl * 8);
    float4 qb = *(const float4*)(Q + (long)b * DIM + cl * 8 + 4);
    qa.x *= scale; qa.y *= scale; qa.z *= scale; qa.w *= scale;
    qb.x *= scale; qb.y *= scale; qb.z *= scale; qb.w *= scale;

    float num[8];
    #pragma unroll
    for (int i = 0; i < 8; i++) num[i] = 0.f;
    float den = 0.f;

    #pragma unroll
    for (int t0 = 0; t0 < 25; t0 += 5) {
        // K loads for 5 item-pairs
        uint4 kr[5];
        #pragma unroll
        for (int j = 0; j < 5; j++)
            kr[j] = *(const uint4*)(KV + (long)sidx[w][2*(t0+j) + half] * 256 + cl * 8);

        // partial scores
        float sc[5];
        #pragma unroll
        for (int j = 0; j < 5; j++) {
            float s;
            s  = qa.x * bflo(kr[j].x) + qa.y * bfhi(kr[j].x);
            s += qa.z * bflo(kr[j].y) + qa.w * bfhi(kr[j].y);
            s += qb.x * bflo(kr[j].z) + qb.y * bfhi(kr[j].z);
            s += qb.z * bflo(kr[j].w) + qb.w * bfhi(kr[j].w);
            sc[j] = s;
        }

        // V loads (independent of the reduction — overlap latency)
        uint4 vr[5];
        #pragma unroll
        for (int j = 0; j < 5; j++)
            vr[j] = *(const uint4*)(KV + (long)sidx[w][2*(t0+j) + half] * 256 + 128 + cl * 8);

        // half-warp reduce scores
        #pragma unroll
        for (int j = 0; j < 5; j++)
            #pragma unroll
            for (int off = 8; off; off >>= 1)
                sc[j] += __shfl_xor_sync(0xffffffffu, sc[j], off);

        // online accumulate: e = exp(s); num += e*v; den += e
        #pragma unroll
        for (int j = 0; j < 5; j++) {
            const float e = __expf(sc[j]);
            den += e;
            num[0] = fmaf(e, bflo(vr[j].x), num[0]);
            num[1] = fmaf(e, bfhi(vr[j].x), num[1]);
            num[2] = fmaf(e, bflo(vr[j].y), num[2]);
            num[3] = fmaf(e, bfhi(vr[j].y), num[3]);
            num[4] = fmaf(e, bflo(vr[j].z), num[4]);
            num[5] = fmaf(e, bfhi(vr[j].z), num[5]);
            num[6] = fmaf(e, bflo(vr[j].w), num[6]);
            num[7] = fmaf(e, bfhi(vr[j].w), num[7]);
        }
    }

    // combine the two half-warps (different items, same columns)
    #pragma unroll
    for (int i = 0; i < 8; i++)
        num[i] += __shfl_xor_sync(0xffffffffu, num[i], 16);
    den += __shfl_xor_sync(0xffffffffu, den, 16);

    if (half == 0) {
        const float inv = 1.0f / den;
        *(float4*)(Y + (long)b * DIM + cl * 8) =
            make_float4(num[0]*inv, num[1]*inv, num[2]*inv, num[3]*inv);
        *(float4*)(Y + (long)b * DIM + cl * 8 + 4) =
            make_float4(num[4]*inv, num[5]*inv, num[6]*inv, num[7]*inv);
    }
}

// ---------------------------------------------------------------------------
// Host launcher (6 launches; node_all BEFORE gemm_item so KV stays L2-hot)
// ---------------------------------------------------------------------------
extern "C" void kernel_launch(void* const* d_in, const int* in_sizes, int n_in,
                              void* d_out, int out_size)
{
    const int*   uids       = (const int*)  d_in[0];
    const int*   u_movies   = (const int*)  d_in[2];
    const float* user_table = (const float*)d_in[3];
    const float* item_table = (const float*)d_in[5];
    const float* gat_wq = (const float*)d_in[6],  *gat_bq = (const float*)d_in[7];
    const float* gat_wk = (const float*)d_in[8],  *gat_bk = (const float*)d_in[9];
    const float* gat_wv = (const float*)d_in[10], *gat_bv = (const float*)d_in[11];
    const float* gat_wo = (const float*)d_in[12], *gat_bo = (const float*)d_in[13];
    const float* sem_wq = (const float*)d_in[14], *sem_bq = (const float*)d_in[15];
    const float* sem_wk = (const float*)d_in[16], *sem_bk = (const float*)d_in[17];
    const float* sem_wv = (const float*)d_in[18], *sem_bv = (const float*)d_in[19];
    const float* sem_wo = (const float*)d_in[20], *sem_bo = (const float*)d_in[21];
    float* out = (float*)d_out;

    __nv_bfloat16* KV;
    unsigned short *Wh0, *Wh1;
    float *Qg, *Q2, *K0, *V0, *K1, *V1, *Y;
    cudaGetSymbolAddress((void**)&KV,  g_KV);
    cudaGetSymbolAddress((void**)&Qg,  g_Qg);
    cudaGetSymbolAddress((void**)&Q2,  g_Q2);
    cudaGetSymbolAddress((void**)&K0,  g_K0);
    cudaGetSymbolAddress((void**)&V0,  g_V0);
    cudaGetSymbolAddress((void**)&K1,  g_K1);
    cudaGetSymbolAddress((void**)&V1,  g_V1);
    cudaGetSymbolAddress((void**)&Y,   g_Y);
    {
        void* p;
        cudaGetSymbolAddress(&p, g_Wh);
        Wh0 = (unsigned short*)p;
        Wh1 = Wh0 + DIM * DIM;
    }

    static bool attr_done = false;
    if (!attr_done) {
        cudaFuncSetAttribute(node_all,  cudaFuncAttributeMaxDynamicSharedMemorySize, NSMEM);
        cudaFuncSetAttribute(gemm_item, cudaFuncAttributeMaxDynamicSharedMemorySize, ISMEM);
        cudaFuncSetAttribute(agg_chain, cudaFuncAttributeMaxDynamicSharedMemorySize, CSMEM);
        cudaFuncSetAttribute(sem_final, cudaFuncAttributeMaxDynamicSharedMemorySize, SSMEM);
        attr_done = true;
    }

    const dim3 blk(256);
    const int gItems = (NITEMS + 127) / 128;     // 782
    const int gBatch = BATCH / 128;              // 128

    // 0: weight transpose + splits
    w_setup<<<64, 256>>>(gat_wq, gat_wk, gat_wv, gat_wo,
                         sem_wq, sem_wk, sem_wv, sem_wo);

    // 1: node transforms FIRST (its 51MB user_table gather would otherwise
    //    evict the KV table from L2 between gemm_item and gat_attn)
    node_all<<<gBatch, blk, NSMEM>>>(user_table, uids,
                                     gat_bq, sem_bq, sem_bk, sem_bv,
                                     Qg, Q2, K0, V0);

    // 2: item K/V -> bf16 KV table (now immediately before its consumer)
    gemm_item<<<dim3(gItems, 2), blk, ISMEM>>>(item_table, Wh0, Wh1,
                                               gat_bk, gat_bv, KV, NITEMS);

    // 3: GAT attention (one-pass online softmax, KV L2-hot)
    gat_attn<<<BATCH / 8, blk>>>(Qg, u_movies, KV, Y);

    // 4: fused Agg -> K1, V1
    agg_chain<<<gBatch, blk, CSMEM>>>(Y, gat_bo, sem_bk, sem_bv, K1, V1);

    // 5: fused sem attention + final projection into d_out
    sem_final<<<gBatch, blk, SSMEM>>>(Q2, K0, K1, V0, V1, sem_bo, out);
}

// round 12
// speedup vs baseline: 1.1461x; 1.0007x over previous
#include <cuda_runtime.h>
#include <cuda_bf16.h>
#include <cuda_fp16.h>
#include <math.h>

// ---------------------------------------------------------------------------
// Problem constants
// ---------------------------------------------------------------------------
#define BATCH   16384
#define NHIST   50
#define DIM     128
#define NITEMS  100000

// ---------------------------------------------------------------------------
// Scratch (static device globals)
// Score-path tensors (Qg,Q2,K0,K1) are bf16; value-path (V0,V1,Y) stay fp32.
// ---------------------------------------------------------------------------
__device__ __nv_bfloat16 g_KV[NITEMS * 256];   // per item: 128 bf16 K | 128 bf16 V
__device__ __nv_bfloat16 g_Qg [BATCH * DIM];
__device__ __nv_bfloat16 g_Q2 [BATCH * DIM];
__device__ __nv_bfloat16 g_K0 [BATCH * DIM];
__device__ __nv_bfloat16 g_K1 [BATCH * DIM];
__device__ float g_V0 [BATCH * DIM];
__device__ float g_V1 [BATCH * DIM];
__device__ float g_Y  [BATCH * DIM];
// bf16 weight splits, transposed to [n][k]: slot 2*w = hi, 2*w+1 = lo
// w: 0=gat_wq 1=gat_wk 2=gat_wv 3=gat_wo 4=sem_wq 5=sem_wk 6=sem_wv 7=sem_wo
__device__ unsigned short g_W4[16][DIM * DIM];
// fp16 transposed weights for the item GEMM: 0=gat_wk, 1=gat_wv
__device__ unsigned short g_Wh[2][DIM * DIM];

// ---------------------------------------------------------------------------
// helpers
// ---------------------------------------------------------------------------
__device__ __forceinline__ unsigned smem_u32(const void* p) {
    unsigned a;
    asm("{ .reg .u64 t; cvta.to.shared.u64 t, %1; cvt.u32.u64 %0, t; }"
        : "=r"(a) : "l"(p));
    return a;
}
__device__ __forceinline__ void ldm4(unsigned& r0, unsigned& r1,
                                     unsigned& r2, unsigned& r3, unsigned addr) {
    asm volatile("ldmatrix.sync.aligned.m8n8.x4.shared.b16 {%0,%1,%2,%3}, [%4];"
                 : "=r"(r0), "=r"(r1), "=r"(r2), "=r"(r3) : "r"(addr));
}
__device__ __forceinline__ void mma_bf16(float* d, const unsigned* a, const unsigned* b) {
    asm volatile("mma.sync.aligned.m16n8k16.row.col.f32.bf16.bf16.f32 "
                 "{%0,%1,%2,%3}, {%4,%5,%6,%7}, {%8,%9}, {%0,%1,%2,%3};"
                 : "+f"(d[0]), "+f"(d[1]), "+f"(d[2]), "+f"(d[3])
                 : "r"(a[0]), "r"(a[1]), "r"(a[2]), "r"(a[3]),
                   "r"(b[0]), "r"(b[1]));
}
__device__ __forceinline__ void mma_f16(float* d, const unsigned* a, const unsigned* b) {
    asm volatile("mma.sync.aligned.m16n8k16.row.col.f32.f16.f16.f32 "
                 "{%0,%1,%2,%3}, {%4,%5,%6,%7}, {%8,%9}, {%0,%1,%2,%3};"
                 : "+f"(d[0]), "+f"(d[1]), "+f"(d[2]), "+f"(d[3])
                 : "r"(a[0]), "r"(a[1]), "r"(a[2]), "r"(a[3]),
                   "r"(b[0]), "r"(b[1]));
}
// smem byte offset for (row, 8-elem 16B chunk kc): 256B rows, XOR swizzle
__device__ __forceinline__ unsigned sw_off(int row, int kc) {
    return (unsigned)(row * 256 + ((kc ^ (row & 7)) << 4));
}
// split 8 fp32 -> two uint4 of bf16 (hi, lo = residual)
__device__ __forceinline__ void split8(const float* xs, uint4& H, uint4& L) {
    unsigned hw[4], lw[4];
    #pragma unroll
    for (int j = 0; j < 4; j++) {
        __nv_bfloat16 h0 = __float2bfloat16(xs[2*j]);
        __nv_bfloat16 h1 = __float2bfloat16(xs[2*j+1]);
        __nv_bfloat16 l0 = __float2bfloat16(xs[2*j]   - __bfloat162float(h0));
        __nv_bfloat16 l1 = __float2bfloat16(xs[2*j+1] - __bfloat162float(h1));
        hw[j] = (unsigned)*(unsigned short*)&h0 | ((unsigned)*(unsigned short*)&h1 << 16);
        lw[j] = (unsigned)*(unsigned short*)&l0 | ((unsigned)*(unsigned short*)&l1 << 16);
    }
    H = make_uint4(hw[0], hw[1], hw[2], hw[3]);
    L = make_uint4(lw[0], lw[1], lw[2], lw[3]);
}
// 8 fp32 -> uint4 of fp16
__device__ __forceinline__ uint4 pack8f16(const float* xs) {
    unsigned hw[4];
    #pragma unroll
    for (int j = 0; j < 4; j++) {
        const unsigned short a = __half_as_ushort(__float2half_rn(xs[2*j]));
        const unsigned short b = __half_as_ushort(__float2half_rn(xs[2*j+1]));
        hw[j] = (unsigned)a | ((unsigned)b << 16);
    }
    return make_uint4(hw[0], hw[1], hw[2], hw[3]);
}
__device__ __forceinline__ unsigned pack_bf2(float a, float b) {
    __nv_bfloat16 x = __float2bfloat16(a), y = __float2bfloat16(b);
    return (unsigned)*(unsigned short*)&x | ((unsigned)*(unsigned short*)&y << 16);
}
// bf16x2 unpack via shift/mask
__device__ __forceinline__ float bflo(unsigned u) { return __uint_as_float(u << 16); }
__device__ __forceinline__ float bfhi(unsigned u) { return __uint_as_float(u & 0xffff0000u); }

// ===========================================================================
// Setup: transpose + split all weight matrices
// ===========================================================================
__global__ void w_setup(const float* w0, const float* w1, const float* w2,
                        const float* w3, const float* w4, const float* w5,
                        const float* w6, const float* w7)
{
    const int i = blockIdx.x * blockDim.x + threadIdx.x;
    if (i >= DIM * DIM) return;
    const float* ws[8] = {w0, w1, w2, w3, w4, w5, w6, w7};
    const int k = i >> 7, n = i & 127;
    const int dst = n * DIM + k;
    #pragma unroll
    for (int w = 0; w < 8; w++) {
        const float a = ws[w][i];
        __nv_bfloat16 h = __float2bfloat16(a);
        __nv_bfloat16 l = __float2bfloat16(a - __bfloat162float(h));
        g_W4[2*w    ][dst] = *(unsigned short*)&h;
        g_W4[2*w + 1][dst] = *(unsigned short*)&l;
    }
    g_Wh[0][dst] = __half_as_ushort(__float2half_rn(w1[i]));   // gat_wk
    g_Wh[1][dst] = __half_as_ushort(__float2half_rn(w2[i]));   // gat_wv
}

// ===========================================================================
// Shared GEMM building blocks. 8 warps (4x2), warp tile 32x64, CTA 128x128.
// ===========================================================================
template<int TERMS>
__device__ __forceinline__ void mma_loop(
    unsigned sb, unsigned oAhi, unsigned oAlo, unsigned oWhi, unsigned oWlo,
    int wm, int wn, int lane, float acc[2][8][4])
{
    #pragma unroll
    for (int i = 0; i < 2; i++)
        #pragma unroll
        for (int j = 0; j < 8; j++)
            #pragma unroll
            for (int q = 0; q < 4; q++) acc[i][j][q] = 0.f;

    #pragma unroll
    for (int ks = 0; ks < 8; ks++) {
        unsigned aH[2][4], aL[2][4], bH[8][2], bL[8][2];
        {
            const int r  = wm * 32 + (lane & 15);
            const int kc = ks * 2 + (lane >> 4);
            ldm4(aH[0][0], aH[0][1], aH[0][2], aH[0][3], sb + oAhi + sw_off(r,      kc));
            ldm4(aH[1][0], aH[1][1], aH[1][2], aH[1][3], sb + oAhi + sw_off(r + 16, kc));
            if (TERMS == 3) {
                ldm4(aL[0][0], aL[0][1], aL[0][2], aL[0][3], sb + oAlo + sw_off(r,      kc));
                ldm4(aL[1][0], aL[1][1], aL[1][2], aL[1][3], sb + oAlo + sw_off(r + 16, kc));
            }
        }
        {
            const int grp  = lane >> 3;
            const int nloc = (lane & 7) + ((grp >> 1) << 3);
            const int kc   = ks * 2 + (grp & 1);
            #pragma unroll
            for (int j = 0; j < 4; j++) {
                const int n = wn * 64 + j * 16 + nloc;
                ldm4(bH[2*j][0], bH[2*j][1], bH[2*j+1][0], bH[2*j+1][1],
                     sb + oWhi + sw_off(n, kc));
                if (TERMS == 3)
                    ldm4(bL[2*j][0], bL[2*j][1], bL[2*j+1][0], bL[2*j+1][1],
                         sb + oWlo + sw_off(n, kc));
            }
        }
        #pragma unroll
        for (int mf = 0; mf < 2; mf++)
            #pragma unroll
            for (int nf = 0; nf < 8; nf++) {
                mma_bf16(acc[mf][nf], aH[mf], bH[nf]);
                if (TERMS == 3) {
                    mma_bf16(acc[mf][nf], aH[mf], bL[nf]);
                    mma_bf16(acc[mf][nf], aL[mf], bH[nf]);
                }
            }
    }
}

__device__ __forceinline__ void epi_f32(
    float acc[2][8][4], const float* sbias, float* C,
    int rowBase, int wm, int wn, int lane, int M)
{
    #pragma unroll
    for (int mf = 0; mf < 2; mf++) {
        const int r0 = rowBase + wm * 32 + mf * 16 + (lane >> 2);
        #pragma unroll
        for (int nf = 0; nf < 8; nf++) {
            const int c  = wn * 64 + nf * 8 + (lane & 3) * 2;
            const float b0 = sbias[c], b1 = sbias[c + 1];
            if (r0 < M)
                *(float2*)(C + (long)r0 * DIM + c) =
                    make_float2(fmaxf(acc[mf][nf][0] + b0, 0.f),
                                fmaxf(acc[mf][nf][1] + b1, 0.f));
            if (r0 + 8 < M)
                *(float2*)(C + (long)(r0 + 8) * DIM + c) =
                    make_float2(fmaxf(acc[mf][nf][2] + b0, 0.f),
                                fmaxf(acc[mf][nf][3] + b1, 0.f));
        }
    }
}

// epilogue writing bf16 (score-path tensors)
__device__ __forceinline__ void epi_bf16(
    float acc[2][8][4], const float* sbias, __nv_bfloat16* C,
    int rowBase, int wm, int wn, int lane, int M)
{
    #pragma unroll
    for (int mf = 0; mf < 2; mf++) {
        const int r0 = rowBase + wm * 32 + mf * 16 + (lane >> 2);
        #pragma unroll
        for (int nf = 0; nf < 8; nf++) {
            const int c  = wn * 64 + nf * 8 + (lane & 3) * 2;
            const float b0 = sbias[c], b1 = sbias[c + 1];
            if (r0 < M)
                *(unsigned*)(C + (long)r0 * DIM + c) =
                    pack_bf2(fmaxf(acc[mf][nf][0] + b0, 0.f),
                             fmaxf(acc[mf][nf][1] + b1, 0.f));
            if (r0 + 8 < M)
                *(unsigned*)(C + (long)(r0 + 8) * DIM + c) =
                    pack_bf2(fmaxf(acc[mf][nf][2] + b0, 0.f),
                             fmaxf(acc[mf][nf][3] + b1, 0.f));
        }
    }
}

__device__ __forceinline__ void stage_w(
    char* sm, unsigned oWhi, unsigned oWlo, int wslot, int tid)
{
    const unsigned short* WH = g_W4[2 * wslot];
    const unsigned short* WL = g_W4[2 * wslot + 1];
    #pragma unroll
    for (int u = 0; u < 8; u++) {
        const int g  = u * 256 + tid;
        const int n  = g >> 4, kc = g & 15;
        const unsigned o = sw_off(n, kc);
        *(uint4*)(sm + oWhi + o) = *(const uint4*)(WH + n * DIM + kc * 8);
        *(uint4*)(sm + oWlo + o) = *(const uint4*)(WL + n * DIM + kc * 8);
    }
}

// ===========================================================================
// Fused node transforms: A staged once; Qg/Q2/K0 (1-term, bf16 out),
// V0 (3-term, fp32 out).
// ===========================================================================
#define NSM_AHI  0u
#define NSM_ALO  32768u
#define NSM_WHI  65536u
#define NSM_WLO  98304u
#define NSM_BIAS 131072u
#define NSMEM    133120

__global__ void __launch_bounds__(256)
node_all(const float* __restrict__ A, const int* __restrict__ gidx,
         const float* __restrict__ bq, const float* __restrict__ bq2,
         const float* __restrict__ bk, const float* __restrict__ bv,
         __nv_bfloat16* __restrict__ Qg, __nv_bfloat16* __restrict__ Q2,
         __nv_bfloat16* __restrict__ K0, float* __restrict__ V0)
{
    extern __shared__ char sm[];
    const unsigned sb = smem_u32(sm);
    const int tid  = threadIdx.x;
    const int wid  = tid >> 5;
    const int lane = tid & 31;
    const int wm   = wid & 3;
    const int wn   = wid >> 2;
    const int rowBase = blockIdx.x * 128;

    if (tid < 128) {
        ((float*)(sm + NSM_BIAS))[tid]        = bq[tid];
        ((float*)(sm + NSM_BIAS + 512))[tid]  = bq2[tid];
        ((float*)(sm + NSM_BIAS + 1024))[tid] = bk[tid];
        ((float*)(sm + NSM_BIAS + 1536))[tid] = bv[tid];
    }

    #pragma unroll
    for (int u = 0; u < 8; u++) {
        const int g  = u * 256 + tid;
        const int r  = g >> 4, kc = g & 15;
        const int src = gidx[rowBase + r];
        const float4 x0 = *(const float4*)(A + (long)src * DIM + kc * 8);
        const float4 x1 = *(const float4*)(A + (long)src * DIM + kc * 8 + 4);
        const float xs[8] = {x0.x, x0.y, x0.z, x0.w, x1.x, x1.y, x1.z, x1.w};
        uint4 H, L;
        split8(xs, H, L);
        const unsigned o = sw_off(r, kc);
        *(uint4*)(sm + NSM_AHI + o) = H;
        *(uint4*)(sm + NSM_ALO + o) = L;
    }
    stage_w(sm, NSM_WHI, NSM_WLO, 0, tid);   // gat_wq
    __syncthreads();

    float acc[2][8][4];

    mma_loop<1>(sb, NSM_AHI, NSM_ALO, NSM_WHI, NSM_WLO, wm, wn, lane, acc);
    __syncthreads();
    stage_w(sm, NSM_WHI, NSM_WLO, 4, tid);   // sem_wq
    epi_bf16(acc, (const float*)(sm + NSM_BIAS), Qg, rowBase, wm, wn, lane, BATCH);
    __syncthreads();

    mma_loop<1>(sb, NSM_AHI, NSM_ALO, NSM_WHI, NSM_WLO, wm, wn, lane, acc);
    __syncthreads();
    stage_w(sm, NSM_WHI, NSM_WLO, 5, tid);   // sem_wk
    epi_bf16(acc, (const float*)(sm + NSM_BIAS + 512), Q2, rowBase, wm, wn, lane, BATCH);
    __syncthreads();

    mma_loop<1>(sb, NSM_AHI, NSM_ALO, NSM_WHI, NSM_WLO, wm, wn, lane, acc);
    __syncthreads();
    stage_w(sm, NSM_WHI, NSM_WLO, 6, tid);   // sem_wv
    epi_bf16(acc, (const float*)(sm + NSM_BIAS + 1024), K0, rowBase, wm, wn, lane, BATCH);
    __syncthreads();

    mma_loop<3>(sb, NSM_AHI, NSM_ALO, NSM_WHI, NSM_WLO, wm, wn, lane, acc);
    epi_f32(acc, (const float*)(sm + NSM_BIAS + 1536), V0, rowBase, wm, wn, lane, BATCH);
}

// ===========================================================================
// Item GEMM: single-term fp16 (output re-rounded to bf16 KV table)
// ===========================================================================
#define ISM_A    0u
#define ISM_W    32768u
#define ISM_BIAS 65536u
#define ISMEM    66048

__global__ void __launch_bounds__(256)
gemm_item(const float* __restrict__ A,
          const unsigned short* __restrict__ W0, const unsigned short* __restrict__ W1,
          const float* __restrict__ b0, const float* __restrict__ b1,
          __nv_bfloat16* __restrict__ KV, int M)
{
    const int y = blockIdx.y;
    const unsigned short* Wt = y ? W1 : W0;
    const float* bias = y ? b1 : b0;
    __nv_bfloat16* Cb = KV + (y ? 128 : 0);

    extern __shared__ char sm[];
    const unsigned sb = smem_u32(sm);
    const int tid  = threadIdx.x;
    const int wid  = tid >> 5;
    const int lane = tid & 31;
    const int wm   = wid & 3;
    const int wn   = wid >> 2;
    const int rowBase = blockIdx.x * 128;

    if (tid < 128) ((float*)(sm + ISM_BIAS))[tid] = bias[tid];

    #pragma unroll
    for (int u = 0; u < 8; u++) {
        const int g  = u * 256 + tid;
        const int r  = g >> 4, kc = g & 15;
        int R = rowBase + r; if (R >= M) R = M - 1;
        const float4 x0 = *(const float4*)(A + (long)R * DIM + kc * 8);
        const float4 x1 = *(const float4*)(A + (long)R * DIM + kc * 8 + 4);
        const float xs[8] = {x0.x, x0.y, x0.z, x0.w, x1.x, x1.y, x1.z, x1.w};
        *(uint4*)(sm + ISM_A + sw_off(r, kc)) = pack8f16(xs);
    }
    #pragma unroll
    for (int u = 0; u < 8; u++) {
        const int g  = u * 256 + tid;
        const int n  = g >> 4, kc = g & 15;
        *(uint4*)(sm + ISM_W + sw_off(n, kc)) = *(const uint4*)(Wt + n * DIM + kc * 8);
    }
    __syncthreads();

    float acc[2][8][4];
    #pragma unroll
    for (int i = 0; i < 2; i++)
        #pragma unroll
        for (int j = 0; j < 8; j++)
            #pragma unroll
            for (int q = 0; q < 4; q++) acc[i][j][q] = 0.f;

    #pragma unroll
    for (int ks = 0; ks < 8; ks++) {
        unsigned aH[2][4], bH[8][2];
        {
            const int r  = wm * 32 + (lane & 15);
            const int kc = ks * 2 + (lane >> 4);
            ldm4(aH[0][0], aH[0][1], aH[0][2], aH[0][3], sb + ISM_A + sw_off(r,      kc));
            ldm4(aH[1][0], aH[1][1], aH[1][2], aH[1][3], sb + ISM_A + sw_off(r + 16, kc));
        }
        {
            const int grp  = lane >> 3;
            const int nloc = (lane & 7) + ((grp >> 1) << 3);
            const int kc   = ks * 2 + (grp & 1);
            #pragma unroll
            for (int j = 0; j < 4; j++) {
                const int n = wn * 64 + j * 16 + nloc;
                ldm4(bH[2*j][0], bH[2*j][1], bH[2*j+1][0], bH[2*j+1][1],
                     sb + ISM_W + sw_off(n, kc));
            }
        }
        #pragma unroll
        for (int mf = 0; mf < 2; mf++)
            #pragma unroll
            for (int nf = 0; nf < 8; nf++)
                mma_f16(acc[mf][nf], aH[mf], bH[nf]);
    }

    const float* sbias = (const float*)(sm + ISM_BIAS);
    #pragma unroll
    for (int mf = 0; mf < 2; mf++) {
        const int r0 = rowBase + wm * 32 + mf * 16 + (lane >> 2);
        #pragma unroll
        for (int nf = 0; nf < 8; nf++) {
            const int c  = wn * 64 + nf * 8 + (lane & 3) * 2;
            const float b0v = sbias[c], b1v = sbias[c + 1];
            if (r0 < M) {
                const unsigned v = pack_bf2(fmaxf(acc[mf][nf][0] + b0v, 0.f),
                                            fmaxf(acc[mf][nf][1] + b1v, 0.f));
                *(unsigned*)(Cb + (long)r0 * 256 + c) = v;
            }
            if (r0 + 8 < M) {
                const unsigned v = pack_bf2(fmaxf(acc[mf][nf][2] + b0v, 0.f),
                                            fmaxf(acc[mf][nf][3] + b1v, 0.f));
                *(unsigned*)(Cb + (long)(r0 + 8) * 256 + c) = v;
            }
        }
    }
}

// ===========================================================================
// Fused chain: Agg (smem) -> K1 (1-term, bf16 out), V1 (3-term, fp32 out)
// ===========================================================================
#define CSM_AHI  0u
#define CSM_ALO  32768u
#define CSM_W1H  65536u
#define CSM_W1L  98304u
#define CSM_W2H  131072u
#define CSM_W2L  163840u
#define CSM_BIAS 196608u
#define CSMEM    198144

__global__ void __launch_bounds__(256)
agg_chain(const float* __restrict__ Y,
          const float* __restrict__ bo, const float* __restrict__ bk,
          const float* __restrict__ bv,
          __nv_bfloat16* __restrict__ K1, float* __restrict__ V1)
{
    extern __shared__ char sm[];
    const unsigned sb = smem_u32(sm);
    const int tid  = threadIdx.x;
    const int wid  = tid >> 5;
    const int lane = tid & 31;
    const int wm   = wid & 3;
    const int wn   = wid >> 2;
    const int rowBase = blockIdx.x * 128;

    if (tid < 128) {
        ((float*)(sm + CSM_BIAS))[tid]       = bo[tid];
        ((float*)(sm + CSM_BIAS + 512))[tid] = bk[tid];
        ((float*)(sm + CSM_BIAS + 1024))[tid]= bv[tid];
    }

    #pragma unroll
    for (int u = 0; u < 8; u++) {
        const int g  = u * 256 + tid;
        const int r  = g >> 4, kc = g & 15;
        const int R = rowBase + r;
        const float4 x0 = *(const float4*)(Y + (long)R * DIM + kc * 8);
        const float4 x1 = *(const float4*)(Y + (long)R * DIM + kc * 8 + 4);
        const float xs[8] = {x0.x, x0.y, x0.z, x0.w, x1.x, x1.y, x1.z, x1.w};
        uint4 H, L;
        split8(xs, H, L);
        const unsigned o = sw_off(r, kc);
        *(uint4*)(sm + CSM_AHI + o) = H;
        *(uint4*)(sm + CSM_ALO + o) = L;
    }
    stage_w(sm, CSM_W1H, CSM_W1L, 3, tid);   // gat_wo
    stage_w(sm, CSM_W2H, CSM_W2L, 5, tid);   // sem_wk
    __syncthreads();

    float acc[2][8][4];

    mma_loop<3>(sb, CSM_AHI, CSM_ALO, CSM_W1H, CSM_W1L, wm, wn, lane, acc);
    __syncthreads();

    {
        const float* sbo = (const float*)(sm + CSM_BIAS);
        #pragma unroll
        for (int mf = 0; mf < 2; mf++) {
            const int r = wm * 32 + mf * 16 + (lane >> 2);
            #pragma unroll
            for (int nf = 0; nf < 8; nf++) {
                const int c  = wn * 64 + nf * 8 + (lane & 3) * 2;
                const float b0 = sbo[c], b1 = sbo[c + 1];
                const float v0 = fmaxf(acc[mf][nf][0] + b0, 0.f);
                const float v1 = fmaxf(acc[mf][nf][1] + b1, 0.f);
                const float v2 = fmaxf(acc[mf][nf][2] + b0, 0.f);
                const float v3 = fmaxf(acc[mf][nf][3] + b1, 0.f);
                const unsigned off0 = sw_off(r,     c >> 3) + (c & 7) * 2;
                const unsigned off1 = sw_off(r + 8, c >> 3) + (c & 7) * 2;
                *(unsigned*)(sm + CSM_AHI + off0) = pack_bf2(v0, v1);
                *(unsigned*)(sm + CSM_AHI + off1) = pack_bf2(v2, v3);
                *(unsigned*)(sm + CSM_ALO + off0) =
                    pack_bf2(v0 - bfhi(pack_bf2(0.f, v0)), v1 - bfhi(pack_bf2(0.f, v1)));
                *(unsigned*)(sm + CSM_ALO + off1) =
                    pack_bf2(v2 - bfhi(pack_bf2(0.f, v2)), v3 - bfhi(pack_bf2(0.f, v3)));
            }
        }
    }
    stage_w(sm, CSM_W1H, CSM_W1L, 6, tid);   // sem_wv
    __syncthreads();

    mma_loop<1>(sb, CSM_AHI, CSM_ALO, CSM_W2H, CSM_W2L, wm, wn, lane, acc);
    epi_bf16(acc, (const float*)(sm + CSM_BIAS + 512), K1, rowBase, wm, wn, lane, BATCH);

    mma_loop<3>(sb, CSM_AHI, CSM_ALO, CSM_W1H, CSM_W1L, wm, wn, lane, acc);
    epi_f32(acc, (const float*)(sm + CSM_BIAS + 1024), V1, rowBase, wm, wn, lane, BATCH);
}

// ===========================================================================
// Fused sem attention + final projection; Q2/K0/K1 read as bf16.
// ===========================================================================
#define SSM_AHI  0u
#define SSM_ALO  32768u
#define SSM_WHI  65536u
#define SSM_WLO  98304u
#define SSM_BIAS 131072u
#define SSMEM    131584

__global__ void __launch_bounds__(256)
sem_final(const __nv_bfloat16* __restrict__ Q2, const __nv_bfloat16* __restrict__ K0,
          const __nv_bfloat16* __restrict__ K1, const float* __restrict__ V0,
          const float* __restrict__ V1, const float* __restrict__ bo2,
          float* __restrict__ out)
{
    extern __shared__ char sm[];
    const unsigned sb = smem_u32(sm);
    const int tid  = threadIdx.x;
    const int wid  = tid >> 5;
    const int lane = tid & 31;
    const int wm   = wid & 3;
    const int wn   = wid >> 2;
    const int rowBase = blockIdx.x * 128;

    if (tid < 128) ((float*)(sm + SSM_BIAS))[tid] = bo2[tid];

    const float scale = 0.08838834764831845f;
    #pragma unroll
    for (int u = 0; u < 8; u++) {
        const int g  = u * 256 + tid;
        const int r  = g >> 4, kc = g & 15;
        const long base = (long)(rowBase + r) * DIM + kc * 8;

        // bf16 score operands: 8 elems = one uint4 each
        const uint4 qu = *(const uint4*)(Q2 + base);
        const uint4 k0u = *(const uint4*)(K0 + base);
        const uint4 k1u = *(const uint4*)(K1 + base);

        float s0, s1;
        s0  = bflo(qu.x)*bflo(k0u.x) + bfhi(qu.x)*bfhi(k0u.x);
        s0 += bflo(qu.y)*bflo(k0u.y) + bfhi(qu.y)*bfhi(k0u.y);
        s0 += bflo(qu.z)*bflo(k0u.z) + bfhi(qu.z)*bfhi(k0u.z);
        s0 += bflo(qu.w)*bflo(k0u.w) + bfhi(qu.w)*bfhi(k0u.w);
        s1  = bflo(qu.x)*bflo(k1u.x) + bfhi(qu.x)*bfhi(k1u.x);
        s1 += bflo(qu.y)*bflo(k1u.y) + bfhi(qu.y)*bfhi(k1u.y);
        s1 += bflo(qu.z)*bflo(k1u.z) + bfhi(qu.z)*bfhi(k1u.z);
        s1 += bflo(qu.w)*bflo(k1u.w) + bfhi(qu.w)*bfhi(k1u.w);

        #pragma unroll
        for (int o = 8; o; o >>= 1) {
            s0 += __shfl_xor_sync(0xffffffffu, s0, o);
            s1 += __shfl_xor_sync(0xffffffffu, s1, o);
        }
        s0 *= scale; s1 *= scale;
        const float m  = fmaxf(s0, s1);
        const float e0 = __expf(s0 - m);
        const float e1 = __expf(s1 - m);
        const float inv = 1.0f / (e0 + e1);
        const float p0 = e0 * inv, p1 = e1 * inv;

        const float4 v0a = *(const float4*)(V0 + base);
        const float4 v0b = *(const float4*)(V0 + base + 4);
        const float4 v1a = *(const float4*)(V1 + base);
        const float4 v1b = *(const float4*)(V1 + base + 4);
        const float xs[8] = {
            p0*v0a.x + p1*v1a.x, p0*v0a.y + p1*v1a.y,
            p0*v0a.z + p1*v1a.z, p0*v0a.w + p1*v1a.w,
            p0*v0b.x + p1*v1b.x, p0*v0b.y + p1*v1b.y,
            p0*v0b.z + p1*v1b.z, p0*v0b.w + p1*v1b.w };
        uint4 H, L;
        split8(xs, H, L);
        const unsigned o = sw_off(r, kc);
        *(uint4*)(sm + SSM_AHI + o) = H;
        *(uint4*)(sm + SSM_ALO + o) = L;
    }
    stage_w(sm, SSM_WHI, SSM_WLO, 7, tid);   // sem_wo
    __syncthreads();

    float acc[2][8][4];
    mma_loop<3>(sb, SSM_AHI, SSM_ALO, SSM_WHI, SSM_WLO, wm, wn, lane, acc);
    epi_f32(acc, (const float*)(sm + SSM_BIAS), out, rowBase, wm, wn, lane, BATCH);
}

// ---------------------------------------------------------------------------
// GAT attention v4b: one-pass online softmax; Q read as bf16 (score path).
// ---------------------------------------------------------------------------
__global__ void __launch_bounds__(256)
gat_attn(const __nv_bfloat16* __restrict__ Q, const int* __restrict__ movies,
         const __nv_bfloat16* __restrict__ KV, float* __restrict__ Y)
{
    const int w    = threadIdx.x >> 5;
    const int lane = threadIdx.x & 31;
    const int half = lane >> 4;
    const int cl   = lane & 15;
    const int b    = blockIdx.x * 8 + w;

    __shared__ int sidx[8][NHIST];

    if (lane < NHIST)      sidx[w][lane]      = movies[(b * NHIST + lane) * 2];
    if (lane + 32 < NHIST) sidx[w][lane + 32] = movies[(b * NHIST + lane + 32) * 2];
    __syncwarp();

    // q chunk (8 bf16 = one uint4), pre-scaled by 1/sqrt(D)
    const float scale = 0.08838834764831845f;
    const uint4 qu = *(const uint4*)(Q + (long)b * DIM + cl * 8);
    float4 qa, qb;
    qa.x = bflo(qu.x) * scale; qa.y = bfhi(qu.x) * scale;
    qa.z = bflo(qu.y) * scale; qa.w = bfhi(qu.y) * scale;
    qb.x = bflo(qu.z) * scale; qb.y = bfhi(qu.z) * scale;
    qb.z = bflo(qu.w) * scale; qb.w = bfhi(qu.w) * scale;

    float num[8];
    #pragma unroll
    for (int i = 0; i < 8; i++) num[i] = 0.f;
    float den = 0.f;

    #pragma unroll
    for (int t0 = 0; t0 < 25; t0 += 5) {
        uint4 kr[5];
        #pragma unroll
        for (int j = 0; j < 5; j++)
            kr[j] = *(const uint4*)(KV + (long)sidx[w][2*(t0+j) + half] * 256 + cl * 8);

        float sc[5];
        #pragma unroll
        for (int j = 0; j < 5; j++) {
            float s;
            s  = qa.x * bflo(kr[j].x) + qa.y * bfhi(kr[j].x);
            s += qa.z * bflo(kr[j].y) + qa.w * bfhi(kr[j].y);
            s += qb.x * bflo(kr[j].z) + qb.y * bfhi(kr[j].z);
            s += qb.z * bflo(kr[j].w) + qb.w * bfhi(kr[j].w);
            sc[j] = s;
        }

        uint4 vr[5];
        #pragma unroll
        for (int j = 0; j < 5; j++)
            vr[j] = *(const uint4*)(KV + (long)sidx[w][2*(t0+j) + half] * 256 + 128 + cl * 8);

        #pragma unroll
        for (int j = 0; j < 5; j++)
            #pragma unroll
            for (int off = 8; off; off >>= 1)
                sc[j] += __shfl_xor_sync(0xffffffffu, sc[j], off);

        #pragma unroll
        for (int j = 0; j < 5; j++) {
            const float e = __expf(sc[j]);
            den += e;
            num[0] = fmaf(e, bflo(vr[j].x), num[0]);
            num[1] = fmaf(e, bfhi(vr[j].x), num[1]);
            num[2] = fmaf(e, bflo(vr[j].y), num[2]);
            num[3] = fmaf(e, bfhi(vr[j].y), num[3]);
            num[4] = fmaf(e, bflo(vr[j].z), num[4]);
            num[5] = fmaf(e, bfhi(vr[j].z), num[5]);
            num[6] = fmaf(e, bflo(vr[j].w), num[6]);
            num[7] = fmaf(e, bfhi(vr[j].w), num[7]);
        }
    }

    #pragma unroll
    for (int i = 0; i < 8; i++)
        num[i] += __shfl_xor_sync(0xffffffffu, num[i], 16);
    den += __shfl_xor_sync(0xffffffffu, den, 16);

    if (half == 0) {
        const float inv = 1.0f / den;
        *(float4*)(Y + (long)b * DIM + cl * 8) =
            make_float4(num[0]*inv, num[1]*inv, num[2]*inv, num[3]*inv);
        *(float4*)(Y + (long)b * DIM + cl * 8 + 4) =
            make_float4(num[4]*inv, num[5]*inv, num[6]*inv, num[7]*inv);
    }
}

// ---------------------------------------------------------------------------
// Host launcher (6 launches)
// ---------------------------------------------------------------------------
extern "C" void kernel_launch(void* const* d_in, const int* in_sizes, int n_in,
                              void* d_out, int out_size)
{
    const int*   uids       = (const int*)  d_in[0];
    const int*   u_movies   = (const int*)  d_in[2];
    const float* user_table = (const float*)d_in[3];
    const float* item_table = (const float*)d_in[5];
    const float* gat_wq = (const float*)d_in[6],  *gat_bq = (const float*)d_in[7];
    const float* gat_wk = (const float*)d_in[8],  *gat_bk = (const float*)d_in[9];
    const float* gat_wv = (const float*)d_in[10], *gat_bv = (const float*)d_in[11];
    const float* gat_wo = (const float*)d_in[12], *gat_bo = (const float*)d_in[13];
    const float* sem_wq = (const float*)d_in[14], *sem_bq = (const float*)d_in[15];
    const float* sem_wk = (const float*)d_in[16], *sem_bk = (const float*)d_in[17];
    const float* sem_wv = (const float*)d_in[18], *sem_bv = (const float*)d_in[19];
    const float* sem_wo = (const float*)d_in[20], *sem_bo = (const float*)d_in[21];
    float* out = (float*)d_out;

    __nv_bfloat16 *KV, *Qg, *Q2, *K0, *K1;
    unsigned short *Wh0, *Wh1;
    float *V0, *V1, *Y;
    cudaGetSymbolAddress((void**)&KV,  g_KV);
    cudaGetSymbolAddress((void**)&Qg,  g_Qg);
    cudaGetSymbolAddress((void**)&Q2,  g_Q2);
    cudaGetSymbolAddress((void**)&K0,  g_K0);
    cudaGetSymbolAddress((void**)&K1,  g_K1);
    cudaGetSymbolAddress((void**)&V0,  g_V0);
    cudaGetSymbolAddress((void**)&V1,  g_V1);
    cudaGetSymbolAddress((void**)&Y,   g_Y);
    {
        void* p;
        cudaGetSymbolAddress(&p, g_Wh);
        Wh0 = (unsigned short*)p;
        Wh1 = Wh0 + DIM * DIM;
    }

    static bool attr_done = false;
    if (!attr_done) {
        cudaFuncSetAttribute(node_all,  cudaFuncAttributeMaxDynamicSharedMemorySize, NSMEM);
        cudaFuncSetAttribute(gemm_item, cudaFuncAttributeMaxDynamicSharedMemorySize, ISMEM);
        cudaFuncSetAttribute(agg_chain, cudaFuncAttributeMaxDynamicSharedMemorySize, CSMEM);
        cudaFuncSetAttribute(sem_final, cudaFuncAttributeMaxDynamicSharedMemorySize, SSMEM);
        attr_done = true;
    }

    const dim3 blk(256);
    const int gItems = (NITEMS + 127) / 128;     // 782
    const int gBatch = BATCH / 128;              // 128

    // 0: weight transpose + splits
    w_setup<<<64, 256>>>(gat_wq, gat_wk, gat_wv, gat_wo,
                         sem_wq, sem_wk, sem_wv, sem_wo);

    // 1: node transforms (Qg/Q2/K0 bf16, V0 fp32)
    node_all<<<gBatch, blk, NSMEM>>>(user_table, uids,
                                     gat_bq, sem_bq, sem_bk, sem_bv,
                                     Qg, Q2, K0, V0);

    // 2: item K/V -> bf16 KV table
    gemm_item<<<dim3(gItems, 2), blk, ISMEM>>>(item_table, Wh0, Wh1,
                                               gat_bk, gat_bv, KV, NITEMS);

    // 3: GAT attention (one-pass online softmax; bf16 Q)
    gat_attn<<<BATCH / 8, blk>>>(Qg, u_movies, KV, Y);

    // 4: fused Agg -> K1 (bf16), V1 (fp32)
    agg_chain<<<gBatch, blk, CSMEM>>>(Y, gat_bo, sem_bk, sem_bv, K1, V1);

    // 5: fused sem attention + final projection into d_out
    sem_final<<<gBatch, blk, SSMEM>>>(Q2, K0, K1, V0, V1, sem_bo, out);
}

// round 13
// speedup vs baseline: 1.1477x; 1.0014x over previous
#include <cuda_runtime.h>
#include <cuda_bf16.h>
#include <cuda_fp16.h>
#include <math.h>

// ---------------------------------------------------------------------------
// Problem constants
// ---------------------------------------------------------------------------
#define BATCH   16384
#define NHIST   50
#define DIM     128
#define NITEMS  100000

// ---------------------------------------------------------------------------
// Scratch (static device globals)
// Score-path tensors (Qg,Q2,K0) bf16; value-path (V0,Y) fp32. K1/V1 now live
// entirely inside the fused tail kernel (no global round-trip).
// ---------------------------------------------------------------------------
__device__ __nv_bfloat16 g_KV[NITEMS * 256];   // per item: 128 bf16 K | 128 bf16 V
__device__ __nv_bfloat16 g_Qg [BATCH * DIM];
__device__ __nv_bfloat16 g_Q2 [BATCH * DIM];
__device__ __nv_bfloat16 g_K0 [BATCH * DIM];
__device__ float g_V0 [BATCH * DIM];
__device__ float g_Y  [BATCH * DIM];
// bf16 weight splits, transposed to [n][k]: slot 2*w = hi, 2*w+1 = lo
// w: 0=gat_wq 1=gat_wk 2=gat_wv 3=gat_wo 4=sem_wq 5=sem_wk 6=sem_wv 7=sem_wo
__device__ unsigned short g_W4[16][DIM * DIM];
// fp16 transposed weights for the item GEMM: 0=gat_wk, 1=gat_wv
__device__ unsigned short g_Wh[2][DIM * DIM];

// ---------------------------------------------------------------------------
// helpers
// ---------------------------------------------------------------------------
__device__ __forceinline__ unsigned smem_u32(const void* p) {
    unsigned a;
    asm("{ .reg .u64 t; cvta.to.shared.u64 t, %1; cvt.u32.u64 %0, t; }"
        : "=r"(a) : "l"(p));
    return a;
}
__device__ __forceinline__ void ldm4(unsigned& r0, unsigned& r1,
                                     unsigned& r2, unsigned& r3, unsigned addr) {
    asm volatile("ldmatrix.sync.aligned.m8n8.x4.shared.b16 {%0,%1,%2,%3}, [%4];"
                 : "=r"(r0), "=r"(r1), "=r"(r2), "=r"(r3) : "r"(addr));
}
__device__ __forceinline__ void mma_bf16(float* d, const unsigned* a, const unsigned* b) {
    asm volatile("mma.sync.aligned.m16n8k16.row.col.f32.bf16.bf16.f32 "
                 "{%0,%1,%2,%3}, {%4,%5,%6,%7}, {%8,%9}, {%0,%1,%2,%3};"
                 : "+f"(d[0]), "+f"(d[1]), "+f"(d[2]), "+f"(d[3])
                 : "r"(a[0]), "r"(a[1]), "r"(a[2]), "r"(a[3]),
                   "r"(b[0]), "r"(b[1]));
}
__device__ __forceinline__ void mma_f16(float* d, const unsigned* a, const unsigned* b) {
    asm volatile("mma.sync.aligned.m16n8k16.row.col.f32.f16.f16.f32 "
                 "{%0,%1,%2,%3}, {%4,%5,%6,%7}, {%8,%9}, {%0,%1,%2,%3};"
                 : "+f"(d[0]), "+f"(d[1]), "+f"(d[2]), "+f"(d[3])
                 : "r"(a[0]), "r"(a[1]), "r"(a[2]), "r"(a[3]),
                   "r"(b[0]), "r"(b[1]));
}
// smem byte offset for (row, 8-elem 16B chunk kc): 256B rows, XOR swizzle
__device__ __forceinline__ unsigned sw_off(int row, int kc) {
    return (unsigned)(row * 256 + ((kc ^ (row & 7)) << 4));
}
// split 8 fp32 -> two uint4 of bf16 (hi, lo = residual)
__device__ __forceinline__ void split8(const float* xs, uint4& H, uint4& L) {
    unsigned hw[4], lw[4];
    #pragma unroll
    for (int j = 0; j < 4; j++) {
        __nv_bfloat16 h0 = __float2bfloat16(xs[2*j]);
        __nv_bfloat16 h1 = __float2bfloat16(xs[2*j+1]);
        __nv_bfloat16 l0 = __float2bfloat16(xs[2*j]   - __bfloat162float(h0));
        __nv_bfloat16 l1 = __float2bfloat16(xs[2*j+1] - __bfloat162float(h1));
        hw[j] = (unsigned)*(unsigned short*)&h0 | ((unsigned)*(unsigned short*)&h1 << 16);
        lw[j] = (unsigned)*(unsigned short*)&l0 | ((unsigned)*(unsigned short*)&l1 << 16);
    }
    H = make_uint4(hw[0], hw[1], hw[2], hw[3]);
    L = make_uint4(lw[0], lw[1], lw[2], lw[3]);
}
// 8 fp32 -> uint4 of fp16
__device__ __forceinline__ uint4 pack8f16(const float* xs) {
    unsigned hw[4];
    #pragma unroll
    for (int j = 0; j < 4; j++) {
        const unsigned short a = __half_as_ushort(__float2half_rn(xs[2*j]));
        const unsigned short b = __half_as_ushort(__float2half_rn(xs[2*j+1]));
        hw[j] = (unsigned)a | ((unsigned)b << 16);
    }
    return make_uint4(hw[0], hw[1], hw[2], hw[3]);
}
__device__ __forceinline__ unsigned pack_bf2(float a, float b) {
    __nv_bfloat16 x = __float2bfloat16(a), y = __float2bfloat16(b);
    return (unsigned)*(unsigned short*)&x | ((unsigned)*(unsigned short*)&y << 16);
}
// bf16x2 unpack via shift/mask
__device__ __forceinline__ float bflo(unsigned u) { return __uint_as_float(u << 16); }
__device__ __forceinline__ float bfhi(unsigned u) { return __uint_as_float(u & 0xffff0000u); }
// write a (v0,v1) pair as bf16 hi + residual lo into split A slots
__device__ __forceinline__ void store_pair_split(
    char* sm, unsigned oHi, unsigned oLo, int r, int c, float v0, float v1)
{
    const unsigned off = sw_off(r, c >> 3) + (c & 7) * 2;
    *(unsigned*)(sm + oHi + off) = pack_bf2(v0, v1);
    *(unsigned*)(sm + oLo + off) =
        pack_bf2(v0 - bfhi(pack_bf2(0.f, v0)), v1 - bfhi(pack_bf2(0.f, v1)));
}

// ===========================================================================
// Setup: transpose + split all weight matrices
// ===========================================================================
__global__ void w_setup(const float* w0, const float* w1, const float* w2,
                        const float* w3, const float* w4, const float* w5,
                        const float* w6, const float* w7)
{
    const int i = blockIdx.x * blockDim.x + threadIdx.x;
    if (i >= DIM * DIM) return;
    const float* ws[8] = {w0, w1, w2, w3, w4, w5, w6, w7};
    const int k = i >> 7, n = i & 127;
    const int dst = n * DIM + k;
    #pragma unroll
    for (int w = 0; w < 8; w++) {
        const float a = ws[w][i];
        __nv_bfloat16 h = __float2bfloat16(a);
        __nv_bfloat16 l = __float2bfloat16(a - __bfloat162float(h));
        g_W4[2*w    ][dst] = *(unsigned short*)&h;
        g_W4[2*w + 1][dst] = *(unsigned short*)&l;
    }
    g_Wh[0][dst] = __half_as_ushort(__float2half_rn(w1[i]));   // gat_wk
    g_Wh[1][dst] = __half_as_ushort(__float2half_rn(w2[i]));   // gat_wv
}

// ===========================================================================
// Shared GEMM building blocks. 8 warps (4x2), warp tile 32x64, CTA 128x128.
// ===========================================================================
template<int TERMS>
__device__ __forceinline__ void mma_loop(
    unsigned sb, unsigned oAhi, unsigned oAlo, unsigned oWhi, unsigned oWlo,
    int wm, int wn, int lane, float acc[2][8][4])
{
    #pragma unroll
    for (int i = 0; i < 2; i++)
        #pragma unroll
        for (int j = 0; j < 8; j++)
            #pragma unroll
            for (int q = 0; q < 4; q++) acc[i][j][q] = 0.f;

    #pragma unroll
    for (int ks = 0; ks < 8; ks++) {
        unsigned aH[2][4], aL[2][4], bH[8][2], bL[8][2];
        {
            const int r  = wm * 32 + (lane & 15);
            const int kc = ks * 2 + (lane >> 4);
            ldm4(aH[0][0], aH[0][1], aH[0][2], aH[0][3], sb + oAhi + sw_off(r,      kc));
            ldm4(aH[1][0], aH[1][1], aH[1][2], aH[1][3], sb + oAhi + sw_off(r + 16, kc));
            if (TERMS == 3) {
                ldm4(aL[0][0], aL[0][1], aL[0][2], aL[0][3], sb + oAlo + sw_off(r,      kc));
                ldm4(aL[1][0], aL[1][1], aL[1][2], aL[1][3], sb + oAlo + sw_off(r + 16, kc));
            }
        }
        {
            const int grp  = lane >> 3;
            const int nloc = (lane & 7) + ((grp >> 1) << 3);
            const int kc   = ks * 2 + (grp & 1);
            #pragma unroll
            for (int j = 0; j < 4; j++) {
                const int n = wn * 64 + j * 16 + nloc;
                ldm4(bH[2*j][0], bH[2*j][1], bH[2*j+1][0], bH[2*j+1][1],
                     sb + oWhi + sw_off(n, kc));
                if (TERMS == 3)
                    ldm4(bL[2*j][0], bL[2*j][1], bL[2*j+1][0], bL[2*j+1][1],
                         sb + oWlo + sw_off(n, kc));
            }
        }
        #pragma unroll
        for (int mf = 0; mf < 2; mf++)
            #pragma unroll
            for (int nf = 0; nf < 8; nf++) {
                mma_bf16(acc[mf][nf], aH[mf], bH[nf]);
                if (TERMS == 3) {
                    mma_bf16(acc[mf][nf], aH[mf], bL[nf]);
                    mma_bf16(acc[mf][nf], aL[mf], bH[nf]);
                }
            }
    }
}

__device__ __forceinline__ void epi_f32(
    float acc[2][8][4], const float* sbias, float* C,
    int rowBase, int wm, int wn, int lane, int M)
{
    #pragma unroll
    for (int mf = 0; mf < 2; mf++) {
        const int r0 = rowBase + wm * 32 + mf * 16 + (lane >> 2);
        #pragma unroll
        for (int nf = 0; nf < 8; nf++) {
            const int c  = wn * 64 + nf * 8 + (lane & 3) * 2;
            const float b0 = sbias[c], b1 = sbias[c + 1];
            if (r0 < M)
                *(float2*)(C + (long)r0 * DIM + c) =
                    make_float2(fmaxf(acc[mf][nf][0] + b0, 0.f),
                                fmaxf(acc[mf][nf][1] + b1, 0.f));
            if (r0 + 8 < M)
                *(float2*)(C + (long)(r0 + 8) * DIM + c) =
                    make_float2(fmaxf(acc[mf][nf][2] + b0, 0.f),
                                fmaxf(acc[mf][nf][3] + b1, 0.f));
        }
    }
}

__device__ __forceinline__ void epi_bf16(
    float acc[2][8][4], const float* sbias, __nv_bfloat16* C,
    int rowBase, int wm, int wn, int lane, int M)
{
    #pragma unroll
    for (int mf = 0; mf < 2; mf++) {
        const int r0 = rowBase + wm * 32 + mf * 16 + (lane >> 2);
        #pragma unroll
        for (int nf = 0; nf < 8; nf++) {
            const int c  = wn * 64 + nf * 8 + (lane & 3) * 2;
            const float b0 = sbias[c], b1 = sbias[c + 1];
            if (r0 < M)
                *(unsigned*)(C + (long)r0 * DIM + c) =
                    pack_bf2(fmaxf(acc[mf][nf][0] + b0, 0.f),
                             fmaxf(acc[mf][nf][1] + b1, 0.f));
            if (r0 + 8 < M)
                *(unsigned*)(C + (long)(r0 + 8) * DIM + c) =
                    pack_bf2(fmaxf(acc[mf][nf][2] + b0, 0.f),
                             fmaxf(acc[mf][nf][3] + b1, 0.f));
        }
    }
}

__device__ __forceinline__ void stage_w(
    char* sm, unsigned oWhi, unsigned oWlo, int wslot, int tid)
{
    const unsigned short* WH = g_W4[2 * wslot];
    const unsigned short* WL = g_W4[2 * wslot + 1];
    #pragma unroll
    for (int u = 0; u < 8; u++) {
        const int g  = u * 256 + tid;
        const int n  = g >> 4, kc = g & 15;
        const unsigned o = sw_off(n, kc);
        *(uint4*)(sm + oWhi + o) = *(const uint4*)(WH + n * DIM + kc * 8);
        *(uint4*)(sm + oWlo + o) = *(const uint4*)(WL + n * DIM + kc * 8);
    }
}

// ===========================================================================
// Fused node transforms (unchanged from R12)
// ===========================================================================
#define NSM_AHI  0u
#define NSM_ALO  32768u
#define NSM_WHI  65536u
#define NSM_WLO  98304u
#define NSM_BIAS 131072u
#define NSMEM    133120

__global__ void __launch_bounds__(256)
node_all(const float* __restrict__ A, const int* __restrict__ gidx,
         const float* __restrict__ bq, const float* __restrict__ bq2,
         const float* __restrict__ bk, const float* __restrict__ bv,
         __nv_bfloat16* __restrict__ Qg, __nv_bfloat16* __restrict__ Q2,
         __nv_bfloat16* __restrict__ K0, float* __restrict__ V0)
{
    extern __shared__ char sm[];
    const unsigned sb = smem_u32(sm);
    const int tid  = threadIdx.x;
    const int wid  = tid >> 5;
    const int lane = tid & 31;
    const int wm   = wid & 3;
    const int wn   = wid >> 2;
    const int rowBase = blockIdx.x * 128;

    if (tid < 128) {
        ((float*)(sm + NSM_BIAS))[tid]        = bq[tid];
        ((float*)(sm + NSM_BIAS + 512))[tid]  = bq2[tid];
        ((float*)(sm + NSM_BIAS + 1024))[tid] = bk[tid];
        ((float*)(sm + NSM_BIAS + 1536))[tid] = bv[tid];
    }

    #pragma unroll
    for (int u = 0; u < 8; u++) {
        const int g  = u * 256 + tid;
        const int r  = g >> 4, kc = g & 15;
        const int src = gidx[rowBase + r];
        const float4 x0 = *(const float4*)(A + (long)src * DIM + kc * 8);
        const float4 x1 = *(const float4*)(A + (long)src * DIM + kc * 8 + 4);
        const float xs[8] = {x0.x, x0.y, x0.z, x0.w, x1.x, x1.y, x1.z, x1.w};
        uint4 H, L;
        split8(xs, H, L);
        const unsigned o = sw_off(r, kc);
        *(uint4*)(sm + NSM_AHI + o) = H;
        *(uint4*)(sm + NSM_ALO + o) = L;
    }
    stage_w(sm, NSM_WHI, NSM_WLO, 0, tid);   // gat_wq
    __syncthreads();

    float acc[2][8][4];

    mma_loop<1>(sb, NSM_AHI, NSM_ALO, NSM_WHI, NSM_WLO, wm, wn, lane, acc);
    __syncthreads();
    stage_w(sm, NSM_WHI, NSM_WLO, 4, tid);   // sem_wq
    epi_bf16(acc, (const float*)(sm + NSM_BIAS), Qg, rowBase, wm, wn, lane, BATCH);
    __syncthreads();

    mma_loop<1>(sb, NSM_AHI, NSM_ALO, NSM_WHI, NSM_WLO, wm, wn, lane, acc);
    __syncthreads();
    stage_w(sm, NSM_WHI, NSM_WLO, 5, tid);   // sem_wk
    epi_bf16(acc, (const float*)(sm + NSM_BIAS + 512), Q2, rowBase, wm, wn, lane, BATCH);
    __syncthreads();

    mma_loop<1>(sb, NSM_AHI, NSM_ALO, NSM_WHI, NSM_WLO, wm, wn, lane, acc);
    __syncthreads();
    stage_w(sm, NSM_WHI, NSM_WLO, 6, tid);   // sem_wv
    epi_bf16(acc, (const float*)(sm + NSM_BIAS + 1024), K0, rowBase, wm, wn, lane, BATCH);
    __syncthreads();

    mma_loop<3>(sb, NSM_AHI, NSM_ALO, NSM_WHI, NSM_WLO, wm, wn, lane, acc);
    epi_f32(acc, (const float*)(sm + NSM_BIAS + 1536), V0, rowBase, wm, wn, lane, BATCH);
}

// ===========================================================================
// Item GEMM (unchanged from R12)
// ===========================================================================
#define ISM_A    0u
#define ISM_W    32768u
#define ISM_BIAS 65536u
#define ISMEM    66048

__global__ void __launch_bounds__(256)
gemm_item(const float* __restrict__ A,
          const unsigned short* __restrict__ W0, const unsigned short* __restrict__ W1,
          const float* __restrict__ b0, const float* __restrict__ b1,
          __nv_bfloat16* __restrict__ KV, int M)
{
    const int y = blockIdx.y;
    const unsigned short* Wt = y ? W1 : W0;
    const float* bias = y ? b1 : b0;
    __nv_bfloat16* Cb = KV + (y ? 128 : 0);

    extern __shared__ char sm[];
    const unsigned sb = smem_u32(sm);
    const int tid  = threadIdx.x;
    const int wid  = tid >> 5;
    const int lane = tid & 31;
    const int wm   = wid & 3;
    const int wn   = wid >> 2;
    const int rowBase = blockIdx.x * 128;

    if (tid < 128) ((float*)(sm + ISM_BIAS))[tid] = bias[tid];

    #pragma unroll
    for (int u = 0; u < 8; u++) {
        const int g  = u * 256 + tid;
        const int r  = g >> 4, kc = g & 15;
        int R = rowBase + r; if (R >= M) R = M - 1;
        const float4 x0 = *(const float4*)(A + (long)R * DIM + kc * 8);
        const float4 x1 = *(const float4*)(A + (long)R * DIM + kc * 8 + 4);
        const float xs[8] = {x0.x, x0.y, x0.z, x0.w, x1.x, x1.y, x1.z, x1.w};
        *(uint4*)(sm + ISM_A + sw_off(r, kc)) = pack8f16(xs);
    }
    #pragma unroll
    for (int u = 0; u < 8; u++) {
        const int g  = u * 256 + tid;
        const int n  = g >> 4, kc = g & 15;
        *(uint4*)(sm + ISM_W + sw_off(n, kc)) = *(const uint4*)(Wt + n * DIM + kc * 8);
    }
    __syncthreads();

    float acc[2][8][4];
    #pragma unroll
    for (int i = 0; i < 2; i++)
        #pragma unroll
        for (int j = 0; j < 8; j++)
            #pragma unroll
            for (int q = 0; q < 4; q++) acc[i][j][q] = 0.f;

    #pragma unroll
    for (int ks = 0; ks < 8; ks++) {
        unsigned aH[2][4], bH[8][2];
        {
            const int r  = wm * 32 + (lane & 15);
            const int kc = ks * 2 + (lane >> 4);
            ldm4(aH[0][0], aH[0][1], aH[0][2], aH[0][3], sb + ISM_A + sw_off(r,      kc));
            ldm4(aH[1][0], aH[1][1], aH[1][2], aH[1][3], sb + ISM_A + sw_off(r + 16, kc));
        }
        {
            const int grp  = lane >> 3;
            const int nloc = (lane & 7) + ((grp >> 1) << 3);
            const int kc   = ks * 2 + (grp & 1);
            #pragma unroll
            for (int j = 0; j < 4; j++) {
                const int n = wn * 64 + j * 16 + nloc;
                ldm4(bH[2*j][0], bH[2*j][1], bH[2*j+1][0], bH[2*j+1][1],
                     sb + ISM_W + sw_off(n, kc));
            }
        }
        #pragma unroll
        for (int mf = 0; mf < 2; mf++)
            #pragma unroll
            for (int nf = 0; nf < 8; nf++)
                mma_f16(acc[mf][nf], aH[mf], bH[nf]);
    }

    const float* sbias = (const float*)(sm + ISM_BIAS);
    #pragma unroll
    for (int mf = 0; mf < 2; mf++) {
        const int r0 = rowBase + wm * 32 + mf * 16 + (lane >> 2);
        #pragma unroll
        for (int nf = 0; nf < 8; nf++) {
            const int c  = wn * 64 + nf * 8 + (lane & 3) * 2;
            const float b0v = sbias[c], b1v = sbias[c + 1];
            if (r0 < M) {
                const unsigned v = pack_bf2(fmaxf(acc[mf][nf][0] + b0v, 0.f),
                                            fmaxf(acc[mf][nf][1] + b1v, 0.f));
                *(unsigned*)(Cb + (long)r0 * 256 + c) = v;
            }
            if (r0 + 8 < M) {
                const unsigned v = pack_bf2(fmaxf(acc[mf][nf][2] + b0v, 0.f),
                                            fmaxf(acc[mf][nf][3] + b1v, 0.f));
                *(unsigned*)(Cb + (long)(r0 + 8) * 256 + c) = v;
            }
        }
    }
}

// ===========================================================================
// FUSED TAIL: Agg = relu(Y@wo+bo)            (3-term, smem-resident)
//          -> K1  = relu(Agg@wk+bk)           (1-term, stashed bf16 in smem)
//          -> V1  = relu(Agg@wv+bv)           (3-term, register-resident)
//          -> p1[r] = softmax2(Q2·K0, Q2·K1)  (per-row, K1 from smem)
//          -> Y2 = (1-p1)*V0 + p1*V1          (fragments -> A slots)
//          -> out = relu(Y2@wo2+bo2)          (3-term)
// smem: A pair 64K | W1 pair 64K | W2 pair 64K (W2H doubles as K1 stash)
//       | biases 2K | p1 512B
// ===========================================================================
#define TSM_AHI  0u
#define TSM_ALO  32768u
#define TSM_W1H  65536u
#define TSM_W1L  98304u
#define TSM_W2H  131072u
#define TSM_W2L  163840u
#define TSM_BIAS 196608u      // bo | bk | bv | bo2 (512B each)
#define TSM_P1   198656u      // 128 floats
#define TSMEM    199168

__global__ void __launch_bounds__(256)
tail_fused(const float* __restrict__ Y,
           const __nv_bfloat16* __restrict__ Q2, const __nv_bfloat16* __restrict__ K0,
           const float* __restrict__ V0,
           const float* __restrict__ bo, const float* __restrict__ bk,
           const float* __restrict__ bv, const float* __restrict__ bo2,
           float* __restrict__ out)
{
    extern __shared__ char sm[];
    const unsigned sb = smem_u32(sm);
    const int tid  = threadIdx.x;
    const int wid  = tid >> 5;
    const int lane = tid & 31;
    const int wm   = wid & 3;
    const int wn   = wid >> 2;
    const int rowBase = blockIdx.x * 128;

    if (tid < 128) {
        ((float*)(sm + TSM_BIAS))[tid]        = bo[tid];
        ((float*)(sm + TSM_BIAS + 512))[tid]  = bk[tid];
        ((float*)(sm + TSM_BIAS + 1024))[tid] = bv[tid];
        ((float*)(sm + TSM_BIAS + 1536))[tid] = bo2[tid];
    }

    // --- stage Y (split) + wo -> W1, wk -> W2 -------------------------------
    #pragma unroll
    for (int u = 0; u < 8; u++) {
        const int g  = u * 256 + tid;
        const int r  = g >> 4, kc = g & 15;
        const int R = rowBase + r;
        const float4 x0 = *(const float4*)(Y + (long)R * DIM + kc * 8);
        const float4 x1 = *(const float4*)(Y + (long)R * DIM + kc * 8 + 4);
        const float xs[8] = {x0.x, x0.y, x0.z, x0.w, x1.x, x1.y, x1.z, x1.w};
        uint4 H, L;
        split8(xs, H, L);
        const unsigned o = sw_off(r, kc);
        *(uint4*)(sm + TSM_AHI + o) = H;
        *(uint4*)(sm + TSM_ALO + o) = L;
    }
    stage_w(sm, TSM_W1H, TSM_W1L, 3, tid);   // gat_wo
    stage_w(sm, TSM_W2H, TSM_W2L, 5, tid);   // sem_wk
    __syncthreads();

    float acc[2][8][4];

    // --- phase 1: Agg = relu(Y@wo+bo), 3-term; write back into A slots ------
    mma_loop<3>(sb, TSM_AHI, TSM_ALO, TSM_W1H, TSM_W1L, wm, wn, lane, acc);
    __syncthreads();
    {
        const float* sbo = (const float*)(sm + TSM_BIAS);
        #pragma unroll
        for (int mf = 0; mf < 2; mf++) {
            const int r = wm * 32 + mf * 16 + (lane >> 2);
            #pragma unroll
            for (int nf = 0; nf < 8; nf++) {
                const int c  = wn * 64 + nf * 8 + (lane & 3) * 2;
                const float b0 = sbo[c], b1 = sbo[c + 1];
                store_pair_split(sm, TSM_AHI, TSM_ALO, r, c,
                                 fmaxf(acc[mf][nf][0] + b0, 0.f),
                                 fmaxf(acc[mf][nf][1] + b1, 0.f));
                store_pair_split(sm, TSM_AHI, TSM_ALO, r + 8, c,
                                 fmaxf(acc[mf][nf][2] + b0, 0.f),
                                 fmaxf(acc[mf][nf][3] + b1, 0.f));
            }
        }
    }
    stage_w(sm, TSM_W1H, TSM_W1L, 6, tid);   // sem_wv (wo no longer needed)
    __syncthreads();

    // --- phase 2: K1 = relu(Agg@wk+bk), 1-term; stash bf16 into W2H ---------
    mma_loop<1>(sb, TSM_AHI, TSM_ALO, TSM_W2H, TSM_W2L, wm, wn, lane, acc);
    __syncthreads();   // all W2 reads done before stash overwrites it
    {
        const float* sbk = (const float*)(sm + TSM_BIAS + 512);
        #pragma unroll
        for (int mf = 0; mf < 2; mf++) {
            const int r = wm * 32 + mf * 16 + (lane >> 2);
            #pragma unroll
            for (int nf = 0; nf < 8; nf++) {
                const int c  = wn * 64 + nf * 8 + (lane & 3) * 2;
                const float b0 = sbk[c], b1 = sbk[c + 1];
                *(unsigned*)(sm + TSM_W2H + r * 256 + c * 2) =
                    pack_bf2(fmaxf(acc[mf][nf][0] + b0, 0.f),
                             fmaxf(acc[mf][nf][1] + b1, 0.f));
                *(unsigned*)(sm + TSM_W2H + (r + 8) * 256 + c * 2) =
                    pack_bf2(fmaxf(acc[mf][nf][2] + b0, 0.f),
                             fmaxf(acc[mf][nf][3] + b1, 0.f));
            }
        }
    }
    __syncthreads();

    // --- phase 3: V1 = Agg@wv (3-term), held in acc registers ---------------
    mma_loop<3>(sb, TSM_AHI, TSM_ALO, TSM_W1H, TSM_W1L, wm, wn, lane, acc);

    // --- phase 4: per-row 2-key softmax -> p1[r] -----------------------------
    {
        const float scale = 0.08838834764831845f;
        #pragma unroll
        for (int u = 0; u < 8; u++) {
            const int g  = u * 256 + tid;
            const int r  = g >> 4, cl = g & 15;
            const long base = (long)(rowBase + r) * DIM + cl * 8;

            const uint4 qu  = *(const uint4*)(Q2 + base);
            const uint4 k0u = *(const uint4*)(K0 + base);
            const uint4 k1u = *(const uint4*)(sm + TSM_W2H + r * 256 + cl * 16);

            float s0, s1;
            s0  = bflo(qu.x)*bflo(k0u.x) + bfhi(qu.x)*bfhi(k0u.x);
            s0 += bflo(qu.y)*bflo(k0u.y) + bfhi(qu.y)*bfhi(k0u.y);
            s0 += bflo(qu.z)*bflo(k0u.z) + bfhi(qu.z)*bfhi(k0u.z);
            s0 += bflo(qu.w)*bflo(k0u.w) + bfhi(qu.w)*bfhi(k0u.w);
            s1  = bflo(qu.x)*bflo(k1u.x) + bfhi(qu.x)*bfhi(k1u.x);
            s1 += bflo(qu.y)*bflo(k1u.y) + bfhi(qu.y)*bfhi(k1u.y);
            s1 += bflo(qu.z)*bflo(k1u.z) + bfhi(qu.z)*bfhi(k1u.z);
            s1 += bflo(qu.w)*bflo(k1u.w) + bfhi(qu.w)*bfhi(k1u.w);

            #pragma unroll
            for (int o = 8; o; o >>= 1) {
                s0 += __shfl_xor_sync(0xffffffffu, s0, o);
                s1 += __shfl_xor_sync(0xffffffffu, s1, o);
            }
            if (cl == 0) {
                s0 *= scale; s1 *= scale;
                const float m  = fmaxf(s0, s1);
                const float e0 = __expf(s0 - m);
                const float e1 = __expf(s1 - m);
                ((float*)(sm + TSM_P1))[r] = e1 / (e0 + e1);
            }
        }
    }
    __syncthreads();

    // --- phase 5: Y2 = (1-p1)*V0 + p1*V1 -> A slots; stage wo2 -> W2 ---------
    {
        const float* sbv = (const float*)(sm + TSM_BIAS + 1024);
        const float* p1s = (const float*)(sm + TSM_P1);
        #pragma unroll
        for (int mf = 0; mf < 2; mf++) {
            const int r = wm * 32 + mf * 16 + (lane >> 2);
            #pragma unroll
            for (int nf = 0; nf < 8; nf++) {
                const int c  = wn * 64 + nf * 8 + (lane & 3) * 2;
                const float b0 = sbv[c], b1 = sbv[c + 1];
                {
                    const float p1 = p1s[r], p0 = 1.f - p1;
                    const float2 v0 = *(const float2*)(V0 + (long)(rowBase + r) * DIM + c);
                    const float v1a = fmaxf(acc[mf][nf][0] + b0, 0.f);
                    const float v1b = fmaxf(acc[mf][nf][1] + b1, 0.f);
                    store_pair_split(sm, TSM_AHI, TSM_ALO, r, c,
                                     p0 * v0.x + p1 * v1a, p0 * v0.y + p1 * v1b);
                }
                {
                    const float p1 = p1s[r + 8], p0 = 1.f - p1;
                    const float2 v0 = *(const float2*)(V0 + (long)(rowBase + r + 8) * DIM + c);
                    const float v1a = fmaxf(acc[mf][nf][2] + b0, 0.f);
                    const float v1b = fmaxf(acc[mf][nf][3] + b1, 0.f);
                    store_pair_split(sm, TSM_AHI, TSM_ALO, r + 8, c,
                                     p0 * v0.x + p1 * v1a, p0 * v0.y + p1 * v1b);
                }
            }
        }
    }
    stage_w(sm, TSM_W2H, TSM_W2L, 7, tid);   // sem_wo (K1 stash no longer needed)
    __syncthreads();

    // --- phase 6: out = relu(Y2@wo2+bo2), 3-term ------------------------------
    mma_loop<3>(sb, TSM_AHI, TSM_ALO, TSM_W2H, TSM_W2L, wm, wn, lane, acc);
    epi_f32(acc, (const float*)(sm + TSM_BIAS + 1536), out, rowBase, wm, wn, lane, BATCH);
}

// ---------------------------------------------------------------------------
// GAT attention v4b (unchanged from R12)
// ---------------------------------------------------------------------------
__global__ void __launch_bounds__(256)
gat_attn(const __nv_bfloat16* __restrict__ Q, const int* __restrict__ movies,
         const __nv_bfloat16* __restrict__ KV, float* __restrict__ Y)
{
    const int w    = threadIdx.x >> 5;
    const int lane = threadIdx.x & 31;
    const int half = lane >> 4;
    const int cl   = lane & 15;
    const int b    = blockIdx.x * 8 + w;

    __shared__ int sidx[8][NHIST];

    if (lane < NHIST)      sidx[w][lane]      = movies[(b * NHIST + lane) * 2];
    if (lane + 32 < NHIST) sidx[w][lane + 32] = movies[(b * NHIST + lane + 32) * 2];
    __syncwarp();

    const float scale = 0.08838834764831845f;
    const uint4 qu = *(const uint4*)(Q + (long)b * DIM + cl * 8);
    float4 qa, qb;
    qa.x = bflo(qu.x) * scale; qa.y = bfhi(qu.x) * scale;
    qa.z = bflo(qu.y) * scale; qa.w = bfhi(qu.y) * scale;
    qb.x = bflo(qu.z) * scale; qb.y = bfhi(qu.z) * scale;
    qb.z = bflo(qu.w) * scale; qb.w = bfhi(qu.w) * scale;

    float num[8];
    #pragma unroll
    for (int i = 0; i < 8; i++) num[i] = 0.f;
    float den = 0.f;

    #pragma unroll
    for (int t0 = 0; t0 < 25; t0 += 5) {
        uint4 kr[5];
        #pragma unroll
        for (int j = 0; j < 5; j++)
            kr[j] = *(const uint4*)(KV + (long)sidx[w][2*(t0+j) + half] * 256 + cl * 8);

        float sc[5];
        #pragma unroll
        for (int j = 0; j < 5; j++) {
            float s;
            s  = qa.x * bflo(kr[j].x) + qa.y * bfhi(kr[j].x);
            s += qa.z * bflo(kr[j].y) + qa.w * bfhi(kr[j].y);
            s += qb.x * bflo(kr[j].z) + qb.y * bfhi(kr[j].z);
            s += qb.z * bflo(kr[j].w) + qb.w * bfhi(kr[j].w);
            sc[j] = s;
        }

        uint4 vr[5];
        #pragma unroll
        for (int j = 0; j < 5; j++)
            vr[j] = *(const uint4*)(KV + (long)sidx[w][2*(t0+j) + half] * 256 + 128 + cl * 8);

        #pragma unroll
        for (int j = 0; j < 5; j++)
            #pragma unroll
            for (int off = 8; off; off >>= 1)
                sc[j] += __shfl_xor_sync(0xffffffffu, sc[j], off);

        #pragma unroll
        for (int j = 0; j < 5; j++) {
            const float e = __expf(sc[j]);
            den += e;
            num[0] = fmaf(e, bflo(vr[j].x), num[0]);
            num[1] = fmaf(e, bfhi(vr[j].x), num[1]);
            num[2] = fmaf(e, bflo(vr[j].y), num[2]);
            num[3] = fmaf(e, bfhi(vr[j].y), num[3]);
            num[4] = fmaf(e, bflo(vr[j].z), num[4]);
            num[5] = fmaf(e, bfhi(vr[j].z), num[5]);
            num[6] = fmaf(e, bflo(vr[j].w), num[6]);
            num[7] = fmaf(e, bfhi(vr[j].w), num[7]);
        }
    }

    #pragma unroll
    for (int i = 0; i < 8; i++)
        num[i] += __shfl_xor_sync(0xffffffffu, num[i], 16);
    den += __shfl_xor_sync(0xffffffffu, den, 16);

    if (half == 0) {
        const float inv = 1.0f / den;
        *(float4*)(Y + (long)b * DIM + cl * 8) =
            make_float4(num[0]*inv, num[1]*inv, num[2]*inv, num[3]*inv);
        *(float4*)(Y + (long)b * DIM + cl * 8 + 4) =
            make_float4(num[4]*inv, num[5]*inv, num[6]*inv, num[7]*inv);
    }
}

// ---------------------------------------------------------------------------
// Host launcher (5 launches)
// ---------------------------------------------------------------------------
extern "C" void kernel_launch(void* const* d_in, const int* in_sizes, int n_in,
                              void* d_out, int out_size)
{
    const int*   uids       = (const int*)  d_in[0];
    const int*   u_movies   = (const int*)  d_in[2];
    const float* user_table = (const float*)d_in[3];
    const float* item_table = (const float*)d_in[5];
    const float* gat_wq = (const float*)d_in[6],  *gat_bq = (const float*)d_in[7];
    const float* gat_wk = (const float*)d_in[8],  *gat_bk = (const float*)d_in[9];
    const float* gat_wv = (const float*)d_in[10], *gat_bv = (const float*)d_in[11];
    const float* gat_wo = (const float*)d_in[12], *gat_bo = (const float*)d_in[13];
    const float* sem_wq = (const float*)d_in[14], *sem_bq = (const float*)d_in[15];
    const float* sem_wk = (const float*)d_in[16], *sem_bk = (const float*)d_in[17];
    const float* sem_wv = (const float*)d_in[18], *sem_bv = (const float*)d_in[19];
    const float* sem_wo = (const float*)d_in[20], *sem_bo = (const float*)d_in[21];
    float* out = (float*)d_out;

    __nv_bfloat16 *KV, *Qg, *Q2, *K0;
    unsigned short *Wh0, *Wh1;
    float *V0, *Y;
    cudaGetSymbolAddress((void**)&KV,  g_KV);
    cudaGetSymbolAddress((void**)&Qg,  g_Qg);
    cudaGetSymbolAddress((void**)&Q2,  g_Q2);
    cudaGetSymbolAddress((void**)&K0,  g_K0);
    cudaGetSymbolAddress((void**)&V0,  g_V0);
    cudaGetSymbolAddress((void**)&Y,   g_Y);
    {
        void* p;
        cudaGetSymbolAddress(&p, g_Wh);
        Wh0 = (unsigned short*)p;
        Wh1 = Wh0 + DIM * DIM;
    }

    static bool attr_done = false;
    if (!attr_done) {
        cudaFuncSetAttribute(node_all,   cudaFuncAttributeMaxDynamicSharedMemorySize, NSMEM);
        cudaFuncSetAttribute(gemm_item,  cudaFuncAttributeMaxDynamicSharedMemorySize, ISMEM);
        cudaFuncSetAttribute(tail_fused, cudaFuncAttributeMaxDynamicSharedMemorySize, TSMEM);
        attr_done = true;
    }

    const dim3 blk(256);
    const int gItems = (NITEMS + 127) / 128;     // 782
    const int gBatch = BATCH / 128;              // 128

    // 0: weight transpose + splits
    w_setup<<<64, 256>>>(gat_wq, gat_wk, gat_wv, gat_wo,
                         sem_wq, sem_wk, sem_wv, sem_wo);

    // 1: node transforms (Qg/Q2/K0 bf16, V0 fp32)
    node_all<<<gBatch, blk, NSMEM>>>(user_table, uids,
                                     gat_bq, sem_bq, sem_bk, sem_bv,
                                     Qg, Q2, K0, V0);

    // 2: item K/V -> bf16 KV table
    gemm_item<<<dim3(gItems, 2), blk, ISMEM>>>(item_table, Wh0, Wh1,
                                               gat_bk, gat_bv, KV, NITEMS);

    // 3: GAT attention (one-pass online softmax)
    gat_attn<<<BATCH / 8, blk>>>(Qg, u_movies, KV, Y);

    // 4: fused tail: Agg -> K1/V1 (smem/regs) -> sem softmax -> final proj
    tail_fused<<<gBatch, blk, TSMEM>>>(Y, Q2, K0, V0,
                                       gat_bo, sem_bk, sem_bv, sem_bo, out);
}